// round 3
// baseline (speedup 1.0000x reference)
#include <cuda_runtime.h>
#include <math.h>

#define BB 8
#define LL 1000
#define DMODEL 512
#define HH 8
#define DK 64
#define PDIM 16
#define DFF 2048
#define NLAYERS 4
#define NPRED 50
#define ROWS (BB*LL)            /* 8000 */
#define LEPS 1e-5f
#define QKSCALE 0.125f          /* 1/sqrt(64) */

/* ------------------------- scratch (device globals; no allocs) ------------------------- */
__device__ float g_h   [ROWS*DMODEL];
__device__ float g_q   [ROWS*DMODEL];
__device__ float g_k   [ROWS*DMODEL];
__device__ float g_v   [ROWS*DMODEL];
__device__ float g_ctx [ROWS*DMODEL];
__device__ float g_y   [ROWS*DMODEL];
__device__ float g_qp  [ROWS*HH*PDIM];
__device__ float g_kp  [ROWS*HH*PDIM];
__device__ float g_ffn [ROWS*DFF];

/* ------------------------- reductions ------------------------- */
__device__ __forceinline__ float block_reduce_sum(float v, float* sbuf) {
    int t = threadIdx.x;
    #pragma unroll
    for (int o = 16; o > 0; o >>= 1) v += __shfl_xor_sync(0xffffffffu, v, o);
    if ((t & 31) == 0) sbuf[t >> 5] = v;
    __syncthreads();
    if (t < 32) {
        float w = (t < (int)(blockDim.x >> 5)) ? sbuf[t] : 0.f;
        #pragma unroll
        for (int o = 16; o > 0; o >>= 1) w += __shfl_xor_sync(0xffffffffu, w, o);
        if (t == 0) sbuf[0] = w;
    }
    __syncthreads();
    float r = sbuf[0];
    __syncthreads();
    return r;
}

/* ------------------------- tf32 helpers ------------------------- */
__device__ __forceinline__ unsigned f2tf(float x) {
    unsigned r;
    asm("cvt.rna.tf32.f32 %0, %1;" : "=r"(r) : "f"(x));
    return r;
}

__device__ __forceinline__ void mma_tf32(float c[4], unsigned a0, unsigned a1,
                                         unsigned a2, unsigned a3,
                                         unsigned b0, unsigned b1) {
    asm volatile(
        "mma.sync.aligned.m16n8k8.row.col.f32.tf32.tf32.f32 "
        "{%0,%1,%2,%3}, {%4,%5,%6,%7}, {%8,%9}, {%0,%1,%2,%3};\n"
        : "+f"(c[0]), "+f"(c[1]), "+f"(c[2]), "+f"(c[3])
        : "r"(a0), "r"(a1), "r"(a2), "r"(a3), "r"(b0), "r"(b1));
}

__device__ __forceinline__ float tanh_fast(float x) {
    float e = __expf(2.f*x);
    return 1.f - 2.f/(e + 1.f);
}

/* ------------------------- embedding: h = x @ emb_w + emb_b + pe ------------------------- */
__global__ void embed_kernel(const float* __restrict__ x, const float* __restrict__ ew,
                             const float* __restrict__ eb, const float* __restrict__ pe,
                             float* __restrict__ h) {
    int r = blockIdx.x;
    int t = threadIdx.x;
    __shared__ float xs[7];
    if (t < 7) xs[t] = x[(size_t)r*7 + t];
    __syncthreads();
    int l = r % LL;
    for (int d = t; d < DMODEL; d += 256) {
        float s = eb[d] + pe[(size_t)l*DMODEL + d];
        #pragma unroll
        for (int f = 0; f < 7; f++) s += xs[f]*ew[(size_t)f*DMODEL + d];
        h[(size_t)r*DMODEL + d] = s;
    }
}

/* ------------------------- tf32 tensor-core GEMM (same as R2) --------------------------- */
#define APITCH 20
#define BPITCH 136
template<int RELU>
__global__ __launch_bounds__(256, 2) void gemm_tf32(const float* __restrict__ A,
                                                    const float* __restrict__ Bm,
                                                    const float* __restrict__ bias,
                                                    float* __restrict__ C,
                                                    int M, int N, int K) {
    __shared__ unsigned As[2][128*APITCH];
    __shared__ unsigned Bs[2][16*BPITCH];

    int tid  = threadIdx.x;
    int lane = tid & 31;
    int wid  = tid >> 5;
    int g    = lane >> 2;
    int tg   = lane & 3;
    int warp_m = wid & 1;
    int warp_n = wid >> 1;

    int row0 = blockIdx.y * 128;
    int col0 = blockIdx.x * 128;

    int ar  = tid >> 2;
    int akq = (tid & 3) * 4;
    int bk  = tid >> 5;
    int bn  = (tid & 31) * 4;

    float acc[4][4][4];
    #pragma unroll
    for (int mt = 0; mt < 4; mt++)
        #pragma unroll
        for (int nt = 0; nt < 4; nt++)
            #pragma unroll
            for (int c = 0; c < 4; c++) acc[mt][nt][c] = 0.f;

    int nslab = K >> 4;
    float4 pa[2], pb[2];

    {
        #pragma unroll
        for (int p = 0; p < 2; p++) {
            int r = row0 + ar + p*64;
            pa[p] = (r < M) ? *(const float4*)(A + (size_t)r*K + akq)
                            : make_float4(0.f,0.f,0.f,0.f);
            int kk = bk + p*8;
            pb[p] = *(const float4*)(Bm + (size_t)kk*N + col0 + bn);
        }
        #pragma unroll
        for (int p = 0; p < 2; p++) {
            unsigned* as = &As[0][(ar + p*64)*APITCH + akq];
            as[0] = f2tf(pa[p].x); as[1] = f2tf(pa[p].y);
            as[2] = f2tf(pa[p].z); as[3] = f2tf(pa[p].w);
            unsigned* bs = &Bs[0][(bk + p*8)*BPITCH + bn];
            bs[0] = f2tf(pb[p].x); bs[1] = f2tf(pb[p].y);
            bs[2] = f2tf(pb[p].z); bs[3] = f2tf(pb[p].w);
        }
    }
    __syncthreads();

    for (int s = 0; s < nslab; s++) {
        int cur = s & 1;
        int nxt = cur ^ 1;
        int kt  = (s + 1) << 4;

        if (s + 1 < nslab) {
            #pragma unroll
            for (int p = 0; p < 2; p++) {
                int r = row0 + ar + p*64;
                pa[p] = (r < M) ? *(const float4*)(A + (size_t)r*K + kt + akq)
                                : make_float4(0.f,0.f,0.f,0.f);
                int kk = kt + bk + p*8;
                pb[p] = *(const float4*)(Bm + (size_t)kk*N + col0 + bn);
            }
        }

        #pragma unroll
        for (int ks = 0; ks < 2; ks++) {
            int kb = ks * 8;
            unsigned af[4][4];
            #pragma unroll
            for (int mt = 0; mt < 4; mt++) {
                int m0 = warp_m*64 + mt*16;
                af[mt][0] = As[cur][(m0 + g    )*APITCH + kb + tg    ];
                af[mt][1] = As[cur][(m0 + g + 8)*APITCH + kb + tg    ];
                af[mt][2] = As[cur][(m0 + g    )*APITCH + kb + tg + 4];
                af[mt][3] = As[cur][(m0 + g + 8)*APITCH + kb + tg + 4];
            }
            unsigned bf[4][2];
            #pragma unroll
            for (int nt = 0; nt < 4; nt++) {
                int n0 = warp_n*32 + nt*8;
                bf[nt][0] = Bs[cur][(kb + tg    )*BPITCH + n0 + g];
                bf[nt][1] = Bs[cur][(kb + tg + 4)*BPITCH + n0 + g];
            }
            #pragma unroll
            for (int mt = 0; mt < 4; mt++)
                #pragma unroll
                for (int nt = 0; nt < 4; nt++)
                    mma_tf32(acc[mt][nt], af[mt][0], af[mt][1], af[mt][2], af[mt][3],
                             bf[nt][0], bf[nt][1]);
        }

        if (s + 1 < nslab) {
            #pragma unroll
            for (int p = 0; p < 2; p++) {
                unsigned* as = &As[nxt][(ar + p*64)*APITCH + akq];
                as[0] = f2tf(pa[p].x); as[1] = f2tf(pa[p].y);
                as[2] = f2tf(pa[p].z); as[3] = f2tf(pa[p].w);
                unsigned* bs = &Bs[nxt][(bk + p*8)*BPITCH + bn];
                bs[0] = f2tf(pb[p].x); bs[1] = f2tf(pb[p].y);
                bs[2] = f2tf(pb[p].z); bs[3] = f2tf(pb[p].w);
            }
        }
        __syncthreads();
    }

    #pragma unroll
    for (int mt = 0; mt < 4; mt++) {
        int gr0 = row0 + warp_m*64 + mt*16 + g;
        int gr1 = gr0 + 8;
        #pragma unroll
        for (int nt = 0; nt < 4; nt++) {
            int gc = col0 + warp_n*32 + nt*8 + tg*2;
            float bsv0 = bias[gc], bsv1 = bias[gc+1];
            if (gr0 < M) {
                float c0 = acc[mt][nt][0] + bsv0;
                float c1 = acc[mt][nt][1] + bsv1;
                if (RELU) { c0 = fmaxf(c0, 0.f); c1 = fmaxf(c1, 0.f); }
                C[(size_t)gr0*N + gc]     = c0;
                C[(size_t)gr0*N + gc + 1] = c1;
            }
            if (gr1 < M) {
                float c2 = acc[mt][nt][2] + bsv0;
                float c3 = acc[mt][nt][3] + bsv1;
                if (RELU) { c2 = fmaxf(c2, 0.f); c3 = fmaxf(c3, 0.f); }
                C[(size_t)gr1*N + gc]     = c2;
                C[(size_t)gr1*N + gc + 1] = c3;
            }
        }
    }
}

/* ------------------------- learned-mask projection: qp = q(head) @ w + b ----------------- */
__global__ void lmproj_kernel(const float* __restrict__ q, const float* __restrict__ w,
                              const float* __restrict__ bias, float* __restrict__ out) {
    __shared__ float row[DMODEL];
    int r = blockIdx.x;
    int t = threadIdx.x;       /* 128 */
    row[t]       = q[(size_t)r*DMODEL + t];
    row[t+128]   = q[(size_t)r*DMODEL + t + 128];
    row[t+256]   = q[(size_t)r*DMODEL + t + 256];
    row[t+384]   = q[(size_t)r*DMODEL + t + 384];
    __syncthreads();
    int h = t >> 4, p = t & 15;
    float s = bias[p];
    #pragma unroll
    for (int d = 0; d < DK; d++) s += row[h*DK + d]*w[d*PDIM + p];
    out[(size_t)r*(HH*PDIM) + t] = s;
}

/* ------------------------- fused flash attention -----------------------------------------
   One block = 64 q-rows of one (b,h). 4 warps, each warp owns 16 q-rows x all 64 kv cols.
   Streams 16 KV tiles of 64, online softmax in registers, PV via smem P roundtrip.
   scores = (q*SCALE).k^T  +  tanh(qp.kp^T), both on tf32 mma.                             */
#define FQP 84
#define FKP 84
#define FVP 72
#define FPP 84
#define SQ_OFF 0
#define SK_OFF (64*FQP)
#define SV_OFF (SK_OFF + 64*FKP)
#define SP_OFF (SV_OFF + 64*FVP)
#define FLASH_SMEM_WORDS (SP_OFF + 64*FPP)
#define FLASH_SMEM_BYTES (FLASH_SMEM_WORDS*4)

__global__ __launch_bounds__(128) void flash_kernel(
    const float* __restrict__ q, const float* __restrict__ k,
    const float* __restrict__ v, const float* __restrict__ qp,
    const float* __restrict__ kp, float* __restrict__ ctx)
{
    extern __shared__ unsigned sm[];
    unsigned* sQ = sm + SQ_OFF;
    unsigned* sK = sm + SK_OFF;
    unsigned* sV = sm + SV_OFF;
    unsigned* sP = sm + SP_OFF;

    int tid  = threadIdx.x;
    int lane = tid & 31, wid = tid >> 5;
    int g = lane >> 2, tg = lane & 3;
    int m0 = wid * 16;
    int l0 = blockIdx.x * 64;
    int bh = blockIdx.y;
    int b = bh >> 3, h = bh & 7;

    /* load Q tile: dims 0..63 = q*SCALE, 64..79 = qp */
    for (int idx = tid; idx < 64*80; idx += 128) {
        int r = idx / 80, d = idx - r*80;
        int l = l0 + r;
        float val = 0.f;
        if (l < LL) {
            if (d < 64) val = q[(size_t)(b*LL + l)*DMODEL + h*DK + d] * QKSCALE;
            else        val = qp[(size_t)(b*LL + l)*(HH*PDIM) + h*PDIM + (d - 64)];
        }
        sQ[r*FQP + d] = f2tf(val);
    }

    float o[8][4];
    #pragma unroll
    for (int nt = 0; nt < 8; nt++)
        #pragma unroll
        for (int c = 0; c < 4; c++) o[nt][c] = 0.f;
    float mrow0 = -1e30f, mrow1 = -1e30f;
    float lrow0 = 0.f,    lrow1 = 0.f;

    __syncthreads();

    for (int it = 0; it < 16; it++) {
        int s0 = it * 64;

        /* load K tile (k dims + kp dims) */
        for (int idx = tid; idx < 64*80; idx += 128) {
            int r = idx / 80, d = idx - r*80;
            int s = s0 + r;
            float val = 0.f;
            if (s < LL) {
                if (d < 64) val = k[(size_t)(b*LL + s)*DMODEL + h*DK + d];
                else        val = kp[(size_t)(b*LL + s)*(HH*PDIM) + h*PDIM + (d - 64)];
            }
            sK[r*FKP + d] = f2tf(val);
        }
        /* load V tile */
        for (int idx = tid; idx < 64*64; idx += 128) {
            int r = idx >> 6, d = idx & 63;
            int s = s0 + r;
            float val = (s < LL) ? v[(size_t)(b*LL + s)*DMODEL + h*DK + d] : 0.f;
            sV[r*FVP + d] = f2tf(val);
        }
        __syncthreads();

        float sc[8][4];

        /* mask part: dims 64..79 (2 k-steps), then tanh, seeding sc */
        unsigned am[2][4];
        #pragma unroll
        for (int kk = 0; kk < 2; kk++) {
            int kb = 64 + kk*8;
            am[kk][0] = sQ[(m0 + g    )*FQP + kb + tg    ];
            am[kk][1] = sQ[(m0 + g + 8)*FQP + kb + tg    ];
            am[kk][2] = sQ[(m0 + g    )*FQP + kb + tg + 4];
            am[kk][3] = sQ[(m0 + g + 8)*FQP + kb + tg + 4];
        }
        #pragma unroll
        for (int nt = 0; nt < 8; nt++) {
            int n0 = nt*8;
            float c4[4] = {0.f, 0.f, 0.f, 0.f};
            #pragma unroll
            for (int kk = 0; kk < 2; kk++) {
                int kb = 64 + kk*8;
                unsigned b0 = sK[(n0 + g)*FKP + kb + tg    ];
                unsigned b1 = sK[(n0 + g)*FKP + kb + tg + 4];
                mma_tf32(c4, am[kk][0], am[kk][1], am[kk][2], am[kk][3], b0, b1);
            }
            sc[nt][0] = tanh_fast(c4[0]);
            sc[nt][1] = tanh_fast(c4[1]);
            sc[nt][2] = tanh_fast(c4[2]);
            sc[nt][3] = tanh_fast(c4[3]);
        }

        /* QK part: dims 0..63 (8 k-steps), accumulate into sc */
        #pragma unroll
        for (int kb8 = 0; kb8 < 8; kb8++) {
            int kb = kb8*8;
            unsigned a0 = sQ[(m0 + g    )*FQP + kb + tg    ];
            unsigned a1 = sQ[(m0 + g + 8)*FQP + kb + tg    ];
            unsigned a2 = sQ[(m0 + g    )*FQP + kb + tg + 4];
            unsigned a3 = sQ[(m0 + g + 8)*FQP + kb + tg + 4];
            #pragma unroll
            for (int nt = 0; nt < 8; nt++) {
                int n0 = nt*8;
                unsigned b0 = sK[(n0 + g)*FKP + kb + tg    ];
                unsigned b1 = sK[(n0 + g)*FKP + kb + tg + 4];
                mma_tf32(sc[nt], a0, a1, a2, a3, b0, b1);
            }
        }

        /* mask out-of-range kv columns (last tile) */
        if (s0 + 64 > LL) {
            #pragma unroll
            for (int nt = 0; nt < 8; nt++) {
                int col = s0 + nt*8 + 2*tg;
                if (col     >= LL) { sc[nt][0] = -1e30f; sc[nt][2] = -1e30f; }
                if (col + 1 >= LL) { sc[nt][1] = -1e30f; sc[nt][3] = -1e30f; }
            }
        }

        /* online softmax: row g (c0,c1), row g+8 (c2,c3); quad holds full row */
        float mx0 = -1e30f, mx1 = -1e30f;
        #pragma unroll
        for (int nt = 0; nt < 8; nt++) {
            mx0 = fmaxf(mx0, fmaxf(sc[nt][0], sc[nt][1]));
            mx1 = fmaxf(mx1, fmaxf(sc[nt][2], sc[nt][3]));
        }
        #pragma unroll
        for (int off = 1; off <= 2; off <<= 1) {
            mx0 = fmaxf(mx0, __shfl_xor_sync(0xffffffffu, mx0, off));
            mx1 = fmaxf(mx1, __shfl_xor_sync(0xffffffffu, mx1, off));
        }
        float mn0 = fmaxf(mrow0, mx0), mn1 = fmaxf(mrow1, mx1);
        float corr0 = __expf(mrow0 - mn0), corr1 = __expf(mrow1 - mn1);
        mrow0 = mn0; mrow1 = mn1;

        float sum0 = 0.f, sum1 = 0.f;
        #pragma unroll
        for (int nt = 0; nt < 8; nt++) {
            float p0 = __expf(sc[nt][0] - mn0);
            float p1 = __expf(sc[nt][1] - mn0);
            float p2 = __expf(sc[nt][2] - mn1);
            float p3 = __expf(sc[nt][3] - mn1);
            sum0 += p0 + p1; sum1 += p2 + p3;
            uint2 w0; w0.x = f2tf(p0); w0.y = f2tf(p1);
            uint2 w1; w1.x = f2tf(p2); w1.y = f2tf(p3);
            *(uint2*)&sP[(m0 + g    )*FPP + nt*8 + 2*tg] = w0;
            *(uint2*)&sP[(m0 + g + 8)*FPP + nt*8 + 2*tg] = w1;
        }
        #pragma unroll
        for (int off = 1; off <= 2; off <<= 1) {
            sum0 += __shfl_xor_sync(0xffffffffu, sum0, off);
            sum1 += __shfl_xor_sync(0xffffffffu, sum1, off);
        }
        lrow0 = lrow0*corr0 + sum0;
        lrow1 = lrow1*corr1 + sum1;
        #pragma unroll
        for (int nt = 0; nt < 8; nt++) {
            o[nt][0] *= corr0; o[nt][1] *= corr0;
            o[nt][2] *= corr1; o[nt][3] *= corr1;
        }
        __syncwarp();

        /* PV: O += P @ V  (P warp-private rows in sP) */
        #pragma unroll
        for (int kb8 = 0; kb8 < 8; kb8++) {
            int kb = kb8*8;
            unsigned a0 = sP[(m0 + g    )*FPP + kb + tg    ];
            unsigned a1 = sP[(m0 + g + 8)*FPP + kb + tg    ];
            unsigned a2 = sP[(m0 + g    )*FPP + kb + tg + 4];
            unsigned a3 = sP[(m0 + g + 8)*FPP + kb + tg + 4];
            #pragma unroll
            for (int nt = 0; nt < 8; nt++) {
                int n0 = nt*8;
                unsigned b0 = sV[(kb + tg    )*FVP + n0 + g];
                unsigned b1 = sV[(kb + tg + 4)*FVP + n0 + g];
                mma_tf32(o[nt], a0, a1, a2, a3, b0, b1);
            }
        }
        __syncthreads();
    }

    /* epilogue: O /= l, write ctx */
    float inv0 = 1.f/lrow0, inv1 = 1.f/lrow1;
    int gl0 = l0 + m0 + g;
    int gl1 = gl0 + 8;
    #pragma unroll
    for (int nt = 0; nt < 8; nt++) {
        int d = h*DK + nt*8 + 2*tg;
        if (gl0 < LL) {
            float2 w; w.x = o[nt][0]*inv0; w.y = o[nt][1]*inv0;
            *(float2*)&ctx[(size_t)(b*LL + gl0)*DMODEL + d] = w;
        }
        if (gl1 < LL) {
            float2 w; w.x = o[nt][2]*inv1; w.y = o[nt][3]*inv1;
            *(float2*)&ctx[(size_t)(b*LL + gl1)*DMODEL + d] = w;
        }
    }
}

/* ------------------------- h = LN(h + res) ------------------------- */
__global__ void ln_residual_kernel(float* __restrict__ h, const float* __restrict__ res,
                                   const float* __restrict__ g, const float* __restrict__ b) {
    __shared__ float sbuf[32];
    int r = blockIdx.x, t = threadIdx.x;
    size_t base = (size_t)r*DMODEL;
    float v0 = h[base + t]       + res[base + t];
    float v1 = h[base + t + 256] + res[base + t + 256];
    float mean = block_reduce_sum(v0 + v1, sbuf) * (1.f/DMODEL);
    float d0 = v0 - mean, d1 = v1 - mean;
    float var = block_reduce_sum(d0*d0 + d1*d1, sbuf) * (1.f/DMODEL);
    float inv = rsqrtf(var + LEPS);
    h[base + t]       = d0*inv*g[t]     + b[t];
    h[base + t + 256] = d1*inv*g[t+256] + b[t+256];
}

/* ------------------------- h = LN(LN(h+y)+y) ------------------------- */
__global__ void double_ln_kernel(float* __restrict__ h, const float* __restrict__ y,
                                 const float* __restrict__ g, const float* __restrict__ b) {
    __shared__ float sbuf[32];
    int r = blockIdx.x, t = threadIdx.x;
    size_t base = (size_t)r*DMODEL;
    float y0 = y[base + t], y1 = y[base + t + 256];
    float t0 = h[base + t] + y0, t1 = h[base + t + 256] + y1;
    float mean = block_reduce_sum(t0 + t1, sbuf) * (1.f/DMODEL);
    float d0 = t0 - mean, d1 = t1 - mean;
    float var = block_reduce_sum(d0*d0 + d1*d1, sbuf) * (1.f/DMODEL);
    float inv = rsqrtf(var + LEPS);
    float h20 = d0*inv*g[t]     + b[t];
    float h21 = d1*inv*g[t+256] + b[t+256];
    float u0 = h20 + y0, u1 = h21 + y1;
    mean = block_reduce_sum(u0 + u1, sbuf) * (1.f/DMODEL);
    d0 = u0 - mean; d1 = u1 - mean;
    var = block_reduce_sum(d0*d0 + d1*d1, sbuf) * (1.f/DMODEL);
    inv = rsqrtf(var + LEPS);
    h[base + t]       = d0*inv*g[t]     + b[t];
    h[base + t + 256] = d1*inv*g[t+256] + b[t+256];
}

/* ------------------------- final: LN(last token) @ fc_w + fc_b ------------------------- */
__global__ void final_kernel(const float* __restrict__ h, const float* __restrict__ gn,
                             const float* __restrict__ bn, const float* __restrict__ fw,
                             const float* __restrict__ fb, float* __restrict__ out) {
    __shared__ float sbuf[32];
    __shared__ float row[DMODEL];
    int b = blockIdx.x, t = threadIdx.x;
    const float* hr = h + (size_t)(b*LL + (LL-1))*DMODEL;
    float v0 = hr[t], v1 = hr[t + 256];
    float mean = block_reduce_sum(v0 + v1, sbuf) * (1.f/DMODEL);
    float d0 = v0 - mean, d1 = v1 - mean;
    float var = block_reduce_sum(d0*d0 + d1*d1, sbuf) * (1.f/DMODEL);
    float inv = rsqrtf(var + LEPS);
    row[t]       = d0*inv*gn[t]     + bn[t];
    row[t + 256] = d1*inv*gn[t+256] + bn[t+256];
    __syncthreads();
    for (int p = t; p < NPRED; p += 256) {
        float s = fb[p];
        for (int d = 0; d < DMODEL; d++) s += row[d]*fw[(size_t)d*NPRED + p];
        out[(size_t)b*NPRED + p] = s;
    }
}

/* ------------------------- launch ------------------------- */
extern "C" void kernel_launch(void* const* d_in, const int* in_sizes, int n_in,
                              void* d_out, int out_size) {
    const float* x     = (const float*)d_in[0];
    const float* emb_w = (const float*)d_in[1];
    const float* emb_b = (const float*)d_in[2];
    const float* pe    = (const float*)d_in[3];
    const float* Wq    = (const float*)d_in[4];
    const float* bq    = (const float*)d_in[5];
    const float* Wk    = (const float*)d_in[6];
    const float* bk    = (const float*)d_in[7];
    const float* Wv    = (const float*)d_in[8];
    const float* bv    = (const float*)d_in[9];
    const float* Wo    = (const float*)d_in[10];
    const float* bo    = (const float*)d_in[11];
    const float* W1    = (const float*)d_in[12];
    const float* b1    = (const float*)d_in[13];
    const float* W2    = (const float*)d_in[14];
    const float* b2    = (const float*)d_in[15];
    const float* g1    = (const float*)d_in[16];
    const float* be1   = (const float*)d_in[17];
    const float* g2    = (const float*)d_in[18];
    const float* be2   = (const float*)d_in[19];
    const float* lm_qw = (const float*)d_in[20];
    const float* lm_qb = (const float*)d_in[21];
    const float* lm_kw = (const float*)d_in[22];
    const float* lm_kb = (const float*)d_in[23];
    const float* gn    = (const float*)d_in[24];
    const float* bn    = (const float*)d_in[25];
    const float* fc_w  = (const float*)d_in[26];
    const float* fc_b  = (const float*)d_in[27];
    float* out = (float*)d_out;

    float *h, *q, *k, *v, *ctx, *y, *qp, *kp, *ffn;
    cudaGetSymbolAddress((void**)&h,   g_h);
    cudaGetSymbolAddress((void**)&q,   g_q);
    cudaGetSymbolAddress((void**)&k,   g_k);
    cudaGetSymbolAddress((void**)&v,   g_v);
    cudaGetSymbolAddress((void**)&ctx, g_ctx);
    cudaGetSymbolAddress((void**)&y,   g_y);
    cudaGetSymbolAddress((void**)&qp,  g_qp);
    cudaGetSymbolAddress((void**)&kp,  g_kp);
    cudaGetSymbolAddress((void**)&ffn, g_ffn);

    cudaFuncSetAttribute(flash_kernel,
                         cudaFuncAttributeMaxDynamicSharedMemorySize, FLASH_SMEM_BYTES);

    embed_kernel<<<ROWS, 256>>>(x, emb_w, emb_b, pe, h);

    dim3 g512(DMODEL/128, (ROWS + 127)/128);
    dim3 gff (DFF/128,    (ROWS + 127)/128);
    dim3 gfl (16, BB*HH);

    for (int i = 0; i < NLAYERS; i++) {
        const float* Wq_i = Wq + (size_t)i*DMODEL*DMODEL;
        const float* Wk_i = Wk + (size_t)i*DMODEL*DMODEL;
        const float* Wv_i = Wv + (size_t)i*DMODEL*DMODEL;
        const float* Wo_i = Wo + (size_t)i*DMODEL*DMODEL;
        const float* bq_i = bq + (size_t)i*DMODEL;
        const float* bk_i = bk + (size_t)i*DMODEL;
        const float* bv_i = bv + (size_t)i*DMODEL;
        const float* bo_i = bo + (size_t)i*DMODEL;
        const float* W1_i = W1 + (size_t)i*DMODEL*DFF;
        const float* b1_i = b1 + (size_t)i*DFF;
        const float* W2_i = W2 + (size_t)i*DFF*DMODEL;
        const float* b2_i = b2 + (size_t)i*DMODEL;
        const float* g1_i = g1 + (size_t)i*DMODEL;
        const float* be1_i= be1+ (size_t)i*DMODEL;
        const float* g2_i = g2 + (size_t)i*DMODEL;
        const float* be2_i= be2+ (size_t)i*DMODEL;

        gemm_tf32<0><<<g512, 256>>>(h, Wq_i, bq_i, q, ROWS, DMODEL, DMODEL);
        gemm_tf32<0><<<g512, 256>>>(h, Wk_i, bk_i, k, ROWS, DMODEL, DMODEL);
        gemm_tf32<0><<<g512, 256>>>(h, Wv_i, bv_i, v, ROWS, DMODEL, DMODEL);

        lmproj_kernel<<<ROWS, 128>>>(q, lm_qw, lm_qb, qp);
        lmproj_kernel<<<ROWS, 128>>>(k, lm_kw, lm_kb, kp);

        flash_kernel<<<gfl, 128, FLASH_SMEM_BYTES>>>(q, k, v, qp, kp, ctx);

        gemm_tf32<0><<<g512, 256>>>(ctx, Wo_i, bo_i, q, ROWS, DMODEL, DMODEL);
        ln_residual_kernel<<<ROWS, 256>>>(h, q, g1_i, be1_i);

        gemm_tf32<1><<<gff, 256>>>(h, W1_i, b1_i, ffn, ROWS, DFF, DMODEL);
        gemm_tf32<0><<<g512, 256>>>(ffn, W2_i, b2_i, y, ROWS, DMODEL, DFF);
        double_ln_kernel<<<ROWS, 256>>>(h, y, g2_i, be2_i);
    }

    final_kernel<<<BB, 256>>>(h, gn, bn, fc_w, fc_b, out);
    (void)in_sizes; (void)n_in; (void)out_size;
}

// round 5
// speedup vs baseline: 1.6426x; 1.6426x over previous
#include <cuda_runtime.h>
#include <math.h>

#define BB 8
#define LL 1000
#define DMODEL 512
#define HH 8
#define DK 64
#define PDIM 16
#define DFF 2048
#define NLAYERS 4
#define NPRED 50
#define ROWS (BB*LL)            /* 8000 */
#define LEPS 1e-5f
#define QKSCALE 0.125f          /* 1/sqrt(64) */

/* ------------------------- scratch (device globals; no allocs) ------------------------- */
__device__ float g_h   [ROWS*DMODEL];
__device__ float g_q   [ROWS*DMODEL];
__device__ float g_k   [ROWS*DMODEL];
__device__ float g_v   [ROWS*DMODEL];
__device__ float g_ctx [ROWS*DMODEL];
__device__ float g_y   [ROWS*DMODEL];
__device__ float g_qp  [ROWS*HH*PDIM];
__device__ float g_kp  [ROWS*HH*PDIM];
__device__ float g_ffn [ROWS*DFF];

/* ------------------------- reductions ------------------------- */
__device__ __forceinline__ float block_reduce_sum(float v, float* sbuf) {
    int t = threadIdx.x;
    #pragma unroll
    for (int o = 16; o > 0; o >>= 1) v += __shfl_xor_sync(0xffffffffu, v, o);
    if ((t & 31) == 0) sbuf[t >> 5] = v;
    __syncthreads();
    if (t < 32) {
        float w = (t < (int)(blockDim.x >> 5)) ? sbuf[t] : 0.f;
        #pragma unroll
        for (int o = 16; o > 0; o >>= 1) w += __shfl_xor_sync(0xffffffffu, w, o);
        if (t == 0) sbuf[0] = w;
    }
    __syncthreads();
    float r = sbuf[0];
    __syncthreads();
    return r;
}

/* ------------------------- tf32 helpers ------------------------- */
__device__ __forceinline__ unsigned f2tf(float x) {
    unsigned r;
    asm("cvt.rna.tf32.f32 %0, %1;" : "=r"(r) : "f"(x));
    return r;
}

__device__ __forceinline__ void mma_tf32(float c[4], unsigned a0, unsigned a1,
                                         unsigned a2, unsigned a3,
                                         unsigned b0, unsigned b1) {
    asm volatile(
        "mma.sync.aligned.m16n8k8.row.col.f32.tf32.tf32.f32 "
        "{%0,%1,%2,%3}, {%4,%5,%6,%7}, {%8,%9}, {%0,%1,%2,%3};\n"
        : "+f"(c[0]), "+f"(c[1]), "+f"(c[2]), "+f"(c[3])
        : "r"(a0), "r"(a1), "r"(a2), "r"(a3), "r"(b0), "r"(b1));
}

__device__ __forceinline__ float tanh_fast(float x) {
    float e = __expf(2.f*x);
    return 1.f - 2.f/(e + 1.f);
}

__device__ __forceinline__ void cp16(unsigned dst_smem, const void* src, int src_bytes) {
    asm volatile("cp.async.cg.shared.global [%0], [%1], 16, %2;"
                 :: "r"(dst_smem), "l"(src), "r"(src_bytes));
}

/* ------------------------- embedding: h = x @ emb_w + emb_b + pe ------------------------- */
__global__ void embed_kernel(const float* __restrict__ x, const float* __restrict__ ew,
                             const float* __restrict__ eb, const float* __restrict__ pe,
                             float* __restrict__ h) {
    int r = blockIdx.x;
    int t = threadIdx.x;
    __shared__ float xs[7];
    if (t < 7) xs[t] = x[(size_t)r*7 + t];
    __syncthreads();
    int l = r % LL;
    for (int d = t; d < DMODEL; d += 256) {
        float s = eb[d] + pe[(size_t)l*DMODEL + d];
        #pragma unroll
        for (int f = 0; f < 7; f++) s += xs[f]*ew[(size_t)f*DMODEL + d];
        h[(size_t)r*DMODEL + d] = s;
    }
}

/* ------------------------- tf32 tensor-core GEMM (same as R2) --------------------------- */
#define APITCH 20
#define BPITCH 136
template<int RELU>
__global__ __launch_bounds__(256, 2) void gemm_tf32(const float* __restrict__ A,
                                                    const float* __restrict__ Bm,
                                                    const float* __restrict__ bias,
                                                    float* __restrict__ C,
                                                    int M, int N, int K) {
    __shared__ unsigned As[2][128*APITCH];
    __shared__ unsigned Bs[2][16*BPITCH];

    int tid  = threadIdx.x;
    int lane = tid & 31;
    int wid  = tid >> 5;
    int g    = lane >> 2;
    int tg   = lane & 3;
    int warp_m = wid & 1;
    int warp_n = wid >> 1;

    int row0 = blockIdx.y * 128;
    int col0 = blockIdx.x * 128;

    int ar  = tid >> 2;
    int akq = (tid & 3) * 4;
    int bk  = tid >> 5;
    int bn  = (tid & 31) * 4;

    float acc[4][4][4];
    #pragma unroll
    for (int mt = 0; mt < 4; mt++)
        #pragma unroll
        for (int nt = 0; nt < 4; nt++)
            #pragma unroll
            for (int c = 0; c < 4; c++) acc[mt][nt][c] = 0.f;

    int nslab = K >> 4;
    float4 pa[2], pb[2];

    {
        #pragma unroll
        for (int p = 0; p < 2; p++) {
            int r = row0 + ar + p*64;
            pa[p] = (r < M) ? *(const float4*)(A + (size_t)r*K + akq)
                            : make_float4(0.f,0.f,0.f,0.f);
            int kk = bk + p*8;
            pb[p] = *(const float4*)(Bm + (size_t)kk*N + col0 + bn);
        }
        #pragma unroll
        for (int p = 0; p < 2; p++) {
            unsigned* as = &As[0][(ar + p*64)*APITCH + akq];
            as[0] = f2tf(pa[p].x); as[1] = f2tf(pa[p].y);
            as[2] = f2tf(pa[p].z); as[3] = f2tf(pa[p].w);
            unsigned* bs = &Bs[0][(bk + p*8)*BPITCH + bn];
            bs[0] = f2tf(pb[p].x); bs[1] = f2tf(pb[p].y);
            bs[2] = f2tf(pb[p].z); bs[3] = f2tf(pb[p].w);
        }
    }
    __syncthreads();

    for (int s = 0; s < nslab; s++) {
        int cur = s & 1;
        int nxt = cur ^ 1;
        int kt  = (s + 1) << 4;

        if (s + 1 < nslab) {
            #pragma unroll
            for (int p = 0; p < 2; p++) {
                int r = row0 + ar + p*64;
                pa[p] = (r < M) ? *(const float4*)(A + (size_t)r*K + kt + akq)
                                : make_float4(0.f,0.f,0.f,0.f);
                int kk = kt + bk + p*8;
                pb[p] = *(const float4*)(Bm + (size_t)kk*N + col0 + bn);
            }
        }

        #pragma unroll
        for (int ks = 0; ks < 2; ks++) {
            int kb = ks * 8;
            unsigned af[4][4];
            #pragma unroll
            for (int mt = 0; mt < 4; mt++) {
                int m0 = warp_m*64 + mt*16;
                af[mt][0] = As[cur][(m0 + g    )*APITCH + kb + tg    ];
                af[mt][1] = As[cur][(m0 + g + 8)*APITCH + kb + tg    ];
                af[mt][2] = As[cur][(m0 + g    )*APITCH + kb + tg + 4];
                af[mt][3] = As[cur][(m0 + g + 8)*APITCH + kb + tg + 4];
            }
            unsigned bf[4][2];
            #pragma unroll
            for (int nt = 0; nt < 4; nt++) {
                int n0 = warp_n*32 + nt*8;
                bf[nt][0] = Bs[cur][(kb + tg    )*BPITCH + n0 + g];
                bf[nt][1] = Bs[cur][(kb + tg + 4)*BPITCH + n0 + g];
            }
            #pragma unroll
            for (int mt = 0; mt < 4; mt++)
                #pragma unroll
                for (int nt = 0; nt < 4; nt++)
                    mma_tf32(acc[mt][nt], af[mt][0], af[mt][1], af[mt][2], af[mt][3],
                             bf[nt][0], bf[nt][1]);
        }

        if (s + 1 < nslab) {
            #pragma unroll
            for (int p = 0; p < 2; p++) {
                unsigned* as = &As[nxt][(ar + p*64)*APITCH + akq];
                as[0] = f2tf(pa[p].x); as[1] = f2tf(pa[p].y);
                as[2] = f2tf(pa[p].z); as[3] = f2tf(pa[p].w);
                unsigned* bs = &Bs[nxt][(bk + p*8)*BPITCH + bn];
                bs[0] = f2tf(pb[p].x); bs[1] = f2tf(pb[p].y);
                bs[2] = f2tf(pb[p].z); bs[3] = f2tf(pb[p].w);
            }
        }
        __syncthreads();
    }

    #pragma unroll
    for (int mt = 0; mt < 4; mt++) {
        int gr0 = row0 + warp_m*64 + mt*16 + g;
        int gr1 = gr0 + 8;
        #pragma unroll
        for (int nt = 0; nt < 4; nt++) {
            int gc = col0 + warp_n*32 + nt*8 + tg*2;
            float bsv0 = bias[gc], bsv1 = bias[gc+1];
            if (gr0 < M) {
                float c0 = acc[mt][nt][0] + bsv0;
                float c1 = acc[mt][nt][1] + bsv1;
                if (RELU) { c0 = fmaxf(c0, 0.f); c1 = fmaxf(c1, 0.f); }
                C[(size_t)gr0*N + gc]     = c0;
                C[(size_t)gr0*N + gc + 1] = c1;
            }
            if (gr1 < M) {
                float c2 = acc[mt][nt][2] + bsv0;
                float c3 = acc[mt][nt][3] + bsv1;
                if (RELU) { c2 = fmaxf(c2, 0.f); c3 = fmaxf(c3, 0.f); }
                C[(size_t)gr1*N + gc]     = c2;
                C[(size_t)gr1*N + gc + 1] = c3;
            }
        }
    }
}

/* ------------------------- learned-mask projection: qp = q(head) @ w + b ----------------- */
__global__ void lmproj_kernel(const float* __restrict__ q, const float* __restrict__ w,
                              const float* __restrict__ bias, float* __restrict__ out) {
    __shared__ float row[DMODEL];
    int r = blockIdx.x;
    int t = threadIdx.x;       /* 128 */
    row[t]       = q[(size_t)r*DMODEL + t];
    row[t+128]   = q[(size_t)r*DMODEL + t + 128];
    row[t+256]   = q[(size_t)r*DMODEL + t + 256];
    row[t+384]   = q[(size_t)r*DMODEL + t + 384];
    __syncthreads();
    int h = t >> 4, p = t & 15;
    float s = bias[p];
    #pragma unroll
    for (int d = 0; d < DK; d++) s += row[h*DK + d]*w[d*PDIM + p];
    out[(size_t)r*(HH*PDIM) + t] = s;
}

/* ------------------------- fused flash attention v2 --------------------------------------
   Block = 128 q-rows of one (b,h); 256 threads / 8 warps, each warp 16 q-rows x 64 kv.
   Q fragments register-resident (loop-invariant). K/V double-buffered via cp.async with
   zfill on tail rows (raw fp32 bits -> tf32 truncation in mma). Online softmax per quad.  */
#define FKP 84
#define FVP 72
#define FPP 84
#define SK_OFF 0
#define SV_OFF (2*64*FKP)
#define SP_OFF (SV_OFF + 2*64*FVP)
#define FLASH_SMEM_WORDS (SP_OFF + 128*FPP)
#define FLASH_SMEM_BYTES (FLASH_SMEM_WORDS*4)

__global__ __launch_bounds__(256) void flash_kernel(
    const float* __restrict__ q, const float* __restrict__ k,
    const float* __restrict__ v, const float* __restrict__ qp,
    const float* __restrict__ kp, float* __restrict__ ctx)
{
    extern __shared__ unsigned sm[];
    unsigned* sP = sm + SP_OFF;

    int tid  = threadIdx.x;
    int lane = tid & 31, wid = tid >> 5;
    int g = lane >> 2, tg = lane & 3;
    int m0 = wid * 16;
    int l0 = blockIdx.x * 128;
    int bh = blockIdx.y;
    int b = bh >> 3, h = bh & 7;

    unsigned smem_base = (unsigned)__cvta_generic_to_shared(sm);

    /* ---- stage Q (scaled) + qp into sP, pull fragments to registers ---- */
    for (int idx = tid; idx < 128*80; idx += 256) {
        int r = idx / 80, d = idx - r*80;
        int l = l0 + r;
        float val = 0.f;
        if (l < LL) {
            if (d < 64) val = q[(size_t)(b*LL + l)*DMODEL + h*DK + d] * QKSCALE;
            else        val = qp[(size_t)(b*LL + l)*(HH*PDIM) + h*PDIM + (d - 64)];
        }
        sP[r*FPP + d] = f2tf(val);
    }
    __syncthreads();

    unsigned qf[10][4];
    #pragma unroll
    for (int kb8 = 0; kb8 < 10; kb8++) {
        int kb = kb8*8;
        qf[kb8][0] = sP[(m0 + g    )*FPP + kb + tg    ];
        qf[kb8][1] = sP[(m0 + g + 8)*FPP + kb + tg    ];
        qf[kb8][2] = sP[(m0 + g    )*FPP + kb + tg + 4];
        qf[kb8][3] = sP[(m0 + g + 8)*FPP + kb + tg + 4];
    }
    __syncthreads();   /* sP now free for P reuse */

    float o[8][4];
    #pragma unroll
    for (int nt = 0; nt < 8; nt++)
        #pragma unroll
        for (int c = 0; c < 4; c++) o[nt][c] = 0.f;
    float mrow0 = -1e30f, mrow1 = -1e30f;
    float lrow0 = 0.f,    lrow1 = 0.f;

    /* async tile loader: K tile 64x80 (k + kp) pitch FKP, V tile 64x64 pitch FVP */
    auto load_tiles = [&](int it, int buf) {
        int s0 = it * 64;
        unsigned kb_addr = smem_base + (SK_OFF + buf*64*FKP)*4u;
        unsigned vb_addr = smem_base + (SV_OFF + buf*64*FVP)*4u;
        for (int c = tid; c < 64*20; c += 256) {
            int r = c / 20, cj = c - r*20;
            int s = s0 + r;
            int ok = (s < LL);
            int sc2 = ok ? s : (LL-1);
            const float* src;
            unsigned dw;
            if (cj < 16) {
                src = k + (size_t)(b*LL + sc2)*DMODEL + h*DK + cj*4;
                dw  = r*FKP + cj*4;
            } else {
                src = kp + (size_t)(b*LL + sc2)*(HH*PDIM) + h*PDIM + (cj-16)*4;
                dw  = r*FKP + 64 + (cj-16)*4;
            }
            cp16(kb_addr + dw*4u, src, ok ? 16 : 0);
        }
        for (int c = tid; c < 64*16; c += 256) {
            int r = c >> 4, cj = c & 15;
            int s = s0 + r;
            int ok = (s < LL);
            int sc2 = ok ? s : (LL-1);
            const float* src = v + (size_t)(b*LL + sc2)*DMODEL + h*DK + cj*4;
            cp16(vb_addr + (r*FVP + cj*4)*4u, src, ok ? 16 : 0);
        }
        asm volatile("cp.async.commit_group;" ::: "memory");
    };

    load_tiles(0, 0);

    for (int it = 0; it < 16; it++) {
        int cur = it & 1;
        if (it + 1 < 16) {
            load_tiles(it + 1, cur ^ 1);
            asm volatile("cp.async.wait_group 1;" ::: "memory");
        } else {
            asm volatile("cp.async.wait_group 0;" ::: "memory");
        }
        __syncthreads();

        const unsigned* bK = sm + SK_OFF + cur*64*FKP;
        const unsigned* bV = sm + SV_OFF + cur*64*FVP;
        int s0 = it * 64;

        float sc[8][4];

        /* mask part first (dims 64..79), tanh seeds sc */
        #pragma unroll
        for (int nt = 0; nt < 8; nt++) {
            int n0 = nt*8;
            float c4[4] = {0.f, 0.f, 0.f, 0.f};
            #pragma unroll
            for (int kk = 8; kk < 10; kk++) {
                int kb = kk*8;
                unsigned b0 = bK[(n0 + g)*FKP + kb + tg    ];
                unsigned b1 = bK[(n0 + g)*FKP + kb + tg + 4];
                mma_tf32(c4, qf[kk][0], qf[kk][1], qf[kk][2], qf[kk][3], b0, b1);
            }
            sc[nt][0] = tanh_fast(c4[0]);
            sc[nt][1] = tanh_fast(c4[1]);
            sc[nt][2] = tanh_fast(c4[2]);
            sc[nt][3] = tanh_fast(c4[3]);
        }

        /* QK accumulate (dims 0..63) */
        #pragma unroll
        for (int kb8 = 0; kb8 < 8; kb8++) {
            int kb = kb8*8;
            #pragma unroll
            for (int nt = 0; nt < 8; nt++) {
                int n0 = nt*8;
                unsigned b0 = bK[(n0 + g)*FKP + kb + tg    ];
                unsigned b1 = bK[(n0 + g)*FKP + kb + tg + 4];
                mma_tf32(sc[nt], qf[kb8][0], qf[kb8][1], qf[kb8][2], qf[kb8][3], b0, b1);
            }
        }

        /* mask invalid kv columns (tail tile) */
        if (s0 + 64 > LL) {
            #pragma unroll
            for (int nt = 0; nt < 8; nt++) {
                int col = s0 + nt*8 + 2*tg;
                if (col     >= LL) { sc[nt][0] = -1e30f; sc[nt][2] = -1e30f; }
                if (col + 1 >= LL) { sc[nt][1] = -1e30f; sc[nt][3] = -1e30f; }
            }
        }

        /* online softmax: rows g and g+8; quad (lanes tg=0..3) holds the full 64 cols */
        float mx0 = -1e30f, mx1 = -1e30f;
        #pragma unroll
        for (int nt = 0; nt < 8; nt++) {
            mx0 = fmaxf(mx0, fmaxf(sc[nt][0], sc[nt][1]));
            mx1 = fmaxf(mx1, fmaxf(sc[nt][2], sc[nt][3]));
        }
        #pragma unroll
        for (int off = 1; off <= 2; off <<= 1) {
            mx0 = fmaxf(mx0, __shfl_xor_sync(0xffffffffu, mx0, off));
            mx1 = fmaxf(mx1, __shfl_xor_sync(0xffffffffu, mx1, off));
        }
        float mn0 = fmaxf(mrow0, mx0), mn1 = fmaxf(mrow1, mx1);
        float corr0 = __expf(mrow0 - mn0), corr1 = __expf(mrow1 - mn1);
        mrow0 = mn0; mrow1 = mn1;

        float sum0 = 0.f, sum1 = 0.f;
        #pragma unroll
        for (int nt = 0; nt < 8; nt++) {
            float p0 = __expf(sc[nt][0] - mn0);
            float p1 = __expf(sc[nt][1] - mn0);
            float p2 = __expf(sc[nt][2] - mn1);
            float p3 = __expf(sc[nt][3] - mn1);
            sum0 += p0 + p1; sum1 += p2 + p3;
            uint2 w0; w0.x = f2tf(p0); w0.y = f2tf(p1);
            uint2 w1; w1.x = f2tf(p2); w1.y = f2tf(p3);
            *(uint2*)&sP[(m0 + g    )*FPP + nt*8 + 2*tg] = w0;
            *(uint2*)&sP[(m0 + g + 8)*FPP + nt*8 + 2*tg] = w1;
        }
        #pragma unroll
        for (int off = 1; off <= 2; off <<= 1) {
            sum0 += __shfl_xor_sync(0xffffffffu, sum0, off);
            sum1 += __shfl_xor_sync(0xffffffffu, sum1, off);
        }
        lrow0 = lrow0*corr0 + sum0;
        lrow1 = lrow1*corr1 + sum1;
        #pragma unroll
        for (int nt = 0; nt < 8; nt++) {
            o[nt][0] *= corr0; o[nt][1] *= corr0;
            o[nt][2] *= corr1; o[nt][3] *= corr1;
        }
        __syncwarp();

        /* PV: O += P @ V  (P rows warp-private in sP) */
        #pragma unroll
        for (int kb8 = 0; kb8 < 8; kb8++) {
            int kb = kb8*8;
            unsigned a0 = sP[(m0 + g    )*FPP + kb + tg    ];
            unsigned a1 = sP[(m0 + g + 8)*FPP + kb + tg    ];
            unsigned a2 = sP[(m0 + g    )*FPP + kb + tg + 4];
            unsigned a3 = sP[(m0 + g + 8)*FPP + kb + tg + 4];
            #pragma unroll
            for (int nt = 0; nt < 8; nt++) {
                int n0 = nt*8;
                unsigned b0 = bV[(kb + tg    )*FVP + n0 + g];
                unsigned b1 = bV[(kb + tg + 4)*FVP + n0 + g];
                mma_tf32(o[nt], a0, a1, a2, a3, b0, b1);
            }
        }
        __syncthreads();
    }

    /* epilogue: O /= l, write ctx */
    float inv0 = 1.f/lrow0, inv1 = 1.f/lrow1;
    int gl0 = l0 + m0 + g;
    int gl1 = gl0 + 8;
    #pragma unroll
    for (int nt = 0; nt < 8; nt++) {
        int d = h*DK + nt*8 + 2*tg;
        if (gl0 < LL) {
            float2 w; w.x = o[nt][0]*inv0; w.y = o[nt][1]*inv0;
            *(float2*)&ctx[(size_t)(b*LL + gl0)*DMODEL + d] = w;
        }
        if (gl1 < LL) {
            float2 w; w.x = o[nt][2]*inv1; w.y = o[nt][3]*inv1;
            *(float2*)&ctx[(size_t)(b*LL + gl1)*DMODEL + d] = w;
        }
    }
}

/* ------------------------- h = LN(h + res) ------------------------- */
__global__ void ln_residual_kernel(float* __restrict__ h, const float* __restrict__ res,
                                   const float* __restrict__ g, const float* __restrict__ b) {
    __shared__ float sbuf[32];
    int r = blockIdx.x, t = threadIdx.x;
    size_t base = (size_t)r*DMODEL;
    float v0 = h[base + t]       + res[base + t];
    float v1 = h[base + t + 256] + res[base + t + 256];
    float mean = block_reduce_sum(v0 + v1, sbuf) * (1.f/DMODEL);
    float d0 = v0 - mean, d1 = v1 - mean;
    float var = block_reduce_sum(d0*d0 + d1*d1, sbuf) * (1.f/DMODEL);
    float inv = rsqrtf(var + LEPS);
    h[base + t]       = d0*inv*g[t]     + b[t];
    h[base + t + 256] = d1*inv*g[t+256] + b[t+256];
}

/* ------------------------- h = LN(LN(h+y)+y) ------------------------- */
__global__ void double_ln_kernel(float* __restrict__ h, const float* __restrict__ y,
                                 const float* __restrict__ g, const float* __restrict__ b) {
    __shared__ float sbuf[32];
    int r = blockIdx.x, t = threadIdx.x;
    size_t base = (size_t)r*DMODEL;
    float y0 = y[base + t], y1 = y[base + t + 256];
    float t0 = h[base + t] + y0, t1 = h[base + t + 256] + y1;
    float mean = block_reduce_sum(t0 + t1, sbuf) * (1.f/DMODEL);
    float d0 = t0 - mean, d1 = t1 - mean;
    float var = block_reduce_sum(d0*d0 + d1*d1, sbuf) * (1.f/DMODEL);
    float inv = rsqrtf(var + LEPS);
    float h20 = d0*inv*g[t]     + b[t];
    float h21 = d1*inv*g[t+256] + b[t+256];
    float u0 = h20 + y0, u1 = h21 + y1;
    mean = block_reduce_sum(u0 + u1, sbuf) * (1.f/DMODEL);
    d0 = u0 - mean; d1 = u1 - mean;
    var = block_reduce_sum(d0*d0 + d1*d1, sbuf) * (1.f/DMODEL);
    inv = rsqrtf(var + LEPS);
    h[base + t]       = d0*inv*g[t]     + b[t];
    h[base + t + 256] = d1*inv*g[t+256] + b[t+256];
}

/* ------------------------- final: LN(last token) @ fc_w + fc_b ------------------------- */
__global__ void final_kernel(const float* __restrict__ h, const float* __restrict__ gn,
                             const float* __restrict__ bn, const float* __restrict__ fw,
                             const float* __restrict__ fb, float* __restrict__ out) {
    __shared__ float sbuf[32];
    __shared__ float row[DMODEL];
    int b = blockIdx.x, t = threadIdx.x;
    const float* hr = h + (size_t)(b*LL + (LL-1))*DMODEL;
    float v0 = hr[t], v1 = hr[t + 256];
    float mean = block_reduce_sum(v0 + v1, sbuf) * (1.f/DMODEL);
    float d0 = v0 - mean, d1 = v1 - mean;
    float var = block_reduce_sum(d0*d0 + d1*d1, sbuf) * (1.f/DMODEL);
    float inv = rsqrtf(var + LEPS);
    row[t]       = d0*inv*gn[t]     + bn[t];
    row[t + 256] = d1*inv*gn[t+256] + bn[t+256];
    __syncthreads();
    for (int p = t; p < NPRED; p += 256) {
        float s = fb[p];
        for (int d = 0; d < DMODEL; d++) s += row[d]*fw[(size_t)d*NPRED + p];
        out[(size_t)b*NPRED + p] = s;
    }
}

/* ------------------------- launch ------------------------- */
extern "C" void kernel_launch(void* const* d_in, const int* in_sizes, int n_in,
                              void* d_out, int out_size) {
    const float* x     = (const float*)d_in[0];
    const float* emb_w = (const float*)d_in[1];
    const float* emb_b = (const float*)d_in[2];
    const float* pe    = (const float*)d_in[3];
    const float* Wq    = (const float*)d_in[4];
    const float* bq    = (const float*)d_in[5];
    const float* Wk    = (const float*)d_in[6];
    const float* bk    = (const float*)d_in[7];
    const float* Wv    = (const float*)d_in[8];
    const float* bv    = (const float*)d_in[9];
    const float* Wo    = (const float*)d_in[10];
    const float* bo    = (const float*)d_in[11];
    const float* W1    = (const float*)d_in[12];
    const float* b1    = (const float*)d_in[13];
    const float* W2    = (const float*)d_in[14];
    const float* b2    = (const float*)d_in[15];
    const float* g1    = (const float*)d_in[16];
    const float* be1   = (const float*)d_in[17];
    const float* g2    = (const float*)d_in[18];
    const float* be2   = (const float*)d_in[19];
    const float* lm_qw = (const float*)d_in[20];
    const float* lm_qb = (const float*)d_in[21];
    const float* lm_kw = (const float*)d_in[22];
    const float* lm_kb = (const float*)d_in[23];
    const float* gn    = (const float*)d_in[24];
    const float* bn    = (const float*)d_in[25];
    const float* fc_w  = (const float*)d_in[26];
    const float* fc_b  = (const float*)d_in[27];
    float* out = (float*)d_out;

    float *h, *q, *k, *v, *ctx, *y, *qp, *kp, *ffn;
    cudaGetSymbolAddress((void**)&h,   g_h);
    cudaGetSymbolAddress((void**)&q,   g_q);
    cudaGetSymbolAddress((void**)&k,   g_k);
    cudaGetSymbolAddress((void**)&v,   g_v);
    cudaGetSymbolAddress((void**)&ctx, g_ctx);
    cudaGetSymbolAddress((void**)&y,   g_y);
    cudaGetSymbolAddress((void**)&qp,  g_qp);
    cudaGetSymbolAddress((void**)&kp,  g_kp);
    cudaGetSymbolAddress((void**)&ffn, g_ffn);

    cudaFuncSetAttribute(flash_kernel,
                         cudaFuncAttributeMaxDynamicSharedMemorySize, FLASH_SMEM_BYTES);

    embed_kernel<<<ROWS, 256>>>(x, emb_w, emb_b, pe, h);

    dim3 g512(DMODEL/128, (ROWS + 127)/128);
    dim3 gff (DFF/128,    (ROWS + 127)/128);
    dim3 gfl (8, BB*HH);

    for (int i = 0; i < NLAYERS; i++) {
        const float* Wq_i = Wq + (size_t)i*DMODEL*DMODEL;
        const float* Wk_i = Wk + (size_t)i*DMODEL*DMODEL;
        const float* Wv_i = Wv + (size_t)i*DMODEL*DMODEL;
        const float* Wo_i = Wo + (size_t)i*DMODEL*DMODEL;
        const float* bq_i = bq + (size_t)i*DMODEL;
        const float* bk_i = bk + (size_t)i*DMODEL;
        const float* bv_i = bv + (size_t)i*DMODEL;
        const float* bo_i = bo + (size_t)i*DMODEL;
        const float* W1_i = W1 + (size_t)i*DMODEL*DFF;
        const float* b1_i = b1 + (size_t)i*DFF;
        const float* W2_i = W2 + (size_t)i*DFF*DMODEL;
        const float* b2_i = b2 + (size_t)i*DMODEL;
        const float* g1_i = g1 + (size_t)i*DMODEL;
        const float* be1_i= be1+ (size_t)i*DMODEL;
        const float* g2_i = g2 + (size_t)i*DMODEL;
        const float* be2_i= be2+ (size_t)i*DMODEL;

        gemm_tf32<0><<<g512, 256>>>(h, Wq_i, bq_i, q, ROWS, DMODEL, DMODEL);
        gemm_tf32<0><<<g512, 256>>>(h, Wk_i, bk_i, k, ROWS, DMODEL, DMODEL);
        gemm_tf32<0><<<g512, 256>>>(h, Wv_i, bv_i, v, ROWS, DMODEL, DMODEL);

        lmproj_kernel<<<ROWS, 128>>>(q, lm_qw, lm_qb, qp);
        lmproj_kernel<<<ROWS, 128>>>(k, lm_kw, lm_kb, kp);

        flash_kernel<<<gfl, 256, FLASH_SMEM_BYTES>>>(q, k, v, qp, kp, ctx);

        gemm_tf32<0><<<g512, 256>>>(ctx, Wo_i, bo_i, q, ROWS, DMODEL, DMODEL);
        ln_residual_kernel<<<ROWS, 256>>>(h, q, g1_i, be1_i);

        gemm_tf32<1><<<gff, 256>>>(h, W1_i, b1_i, ffn, ROWS, DFF, DMODEL);
        gemm_tf32<0><<<g512, 256>>>(ffn, W2_i, b2_i, y, ROWS, DMODEL, DFF);
        double_ln_kernel<<<ROWS, 256>>>(h, y, g2_i, be2_i);
    }

    final_kernel<<<BB, 256>>>(h, gn, bn, fc_w, fc_b, out);
    (void)in_sizes; (void)n_in; (void)out_size;
}

// round 8
// speedup vs baseline: 1.6724x; 1.0182x over previous
#include <cuda_runtime.h>
#include <math.h>

#define BB 8
#define LL 1000
#define DMODEL 512
#define HH 8
#define DK 64
#define PDIM 16
#define DFF 2048
#define NLAYERS 4
#define NPRED 50
#define ROWS (BB*LL)            /* 8000 */
#define LEPS 1e-5f
#define QKSCALE 0.125f          /* 1/sqrt(64) */

/* ------------------------- scratch (device globals; no allocs) ------------------------- */
__device__ float g_h   [ROWS*DMODEL];
__device__ float g_q   [ROWS*DMODEL];
__device__ float g_k   [ROWS*DMODEL];
__device__ float g_v   [ROWS*DMODEL];
__device__ float g_ctx [ROWS*DMODEL];
__device__ float g_y   [ROWS*DMODEL];
__device__ float g_qp  [ROWS*HH*PDIM];
__device__ float g_kp  [ROWS*HH*PDIM];
__device__ float g_ffn [ROWS*DFF];

/* ------------------------- reductions ------------------------- */
__device__ __forceinline__ float block_reduce_sum(float v, float* sbuf) {
    int t = threadIdx.x;
    #pragma unroll
    for (int o = 16; o > 0; o >>= 1) v += __shfl_xor_sync(0xffffffffu, v, o);
    if ((t & 31) == 0) sbuf[t >> 5] = v;
    __syncthreads();
    if (t < 32) {
        float w = (t < (int)(blockDim.x >> 5)) ? sbuf[t] : 0.f;
        #pragma unroll
        for (int o = 16; o > 0; o >>= 1) w += __shfl_xor_sync(0xffffffffu, w, o);
        if (t == 0) sbuf[0] = w;
    }
    __syncthreads();
    float r = sbuf[0];
    __syncthreads();
    return r;
}

/* ------------------------- tf32 helpers ------------------------- */
__device__ __forceinline__ unsigned f2tf(float x) {
    unsigned r;
    asm("cvt.rna.tf32.f32 %0, %1;" : "=r"(r) : "f"(x));
    return r;
}

__device__ __forceinline__ void mma_tf32(float c[4], unsigned a0, unsigned a1,
                                         unsigned a2, unsigned a3,
                                         unsigned b0, unsigned b1) {
    asm volatile(
        "mma.sync.aligned.m16n8k8.row.col.f32.tf32.tf32.f32 "
        "{%0,%1,%2,%3}, {%4,%5,%6,%7}, {%8,%9}, {%0,%1,%2,%3};\n"
        : "+f"(c[0]), "+f"(c[1]), "+f"(c[2]), "+f"(c[3])
        : "r"(a0), "r"(a1), "r"(a2), "r"(a3), "r"(b0), "r"(b1));
}

__device__ __forceinline__ float tanh_fast(float x) {
    float e = __expf(2.f*x);
    return 1.f - 2.f/(e + 1.f);
}

__device__ __forceinline__ void cp16(unsigned dst_smem, const void* src, int src_bytes) {
    asm volatile("cp.async.cg.shared.global [%0], [%1], 16, %2;"
                 :: "r"(dst_smem), "l"(src), "r"(src_bytes));
}

/* ------------------------- embedding: h = x @ emb_w + emb_b + pe ------------------------- */
__global__ void embed_kernel(const float* __restrict__ x, const float* __restrict__ ew,
                             const float* __restrict__ eb, const float* __restrict__ pe,
                             float* __restrict__ h) {
    int r = blockIdx.x;
    int t = threadIdx.x;
    __shared__ float xs[7];
    if (t < 7) xs[t] = x[(size_t)r*7 + t];
    __syncthreads();
    int l = r % LL;
    for (int d = t; d < DMODEL; d += 256) {
        float s = eb[d] + pe[(size_t)l*DMODEL + d];
        #pragma unroll
        for (int f = 0; f < 7; f++) s += xs[f]*ew[(size_t)f*DMODEL + d];
        h[(size_t)r*DMODEL + d] = s;
    }
}

/* ------------------------- tf32 GEMM v3: fragment-packed smem ----------------------------
   Same numerics as R5 (cvt.rna at staging). Fragments stored pre-packed so mma operand
   loads are LDS.128: A 4/k-step, B 2/k-step (was 16+8 scalar LDS).
   A layout: block(wm*2+ks) stride 648w; slot(g*4+tg) stride 20w; word mt*4 + c.
   B layout: block(wn*2+ks) stride 388w; slot(g*4+tg) stride 12w; word c*4 + nt.         */
#define A_BLK 648
#define A_SLOT 20
#define B_BLK 388
#define B_SLOT 12
#define A_WORDS (4*A_BLK)   /* 2592 */
#define B_WORDS (8*B_BLK)   /* 3104 */
template<int RELU>
__global__ __launch_bounds__(256, 2) void gemm_tf32(const float* __restrict__ A,
                                                    const float* __restrict__ Bm,
                                                    const float* __restrict__ bias,
                                                    float* __restrict__ C,
                                                    int M, int N, int K) {
    __shared__ __align__(16) unsigned As[2][A_WORDS];
    __shared__ __align__(16) unsigned Bs[2][B_WORDS];

    int tid  = threadIdx.x;
    int lane = tid & 31;
    int wid  = tid >> 5;
    int g    = lane >> 2;
    int tg   = lane & 3;
    int warp_m = wid & 1;
    int warp_n = wid >> 1;

    int row0 = blockIdx.y * 128;
    int col0 = blockIdx.x * 128;

    int ar  = tid >> 2;           /* 0..63: A tile row (and +64) */
    int akq = (tid & 3) * 4;      /* k offset, float4 */
    int bk  = tid >> 5;           /* 0..7: B k-row (and +8) */
    int bn  = (tid & 31) * 4;     /* n offset, float4 */

    /* ---- precomputed A store bases (per p): r -> (wm,mt,g,halfm); akq -> (ks,halfk) ---- */
    int aks   = akq >> 3;
    int ahalf = (akq >> 2) & 1;
    unsigned a_st[2];
    #pragma unroll
    for (int p = 0; p < 2; p++) {
        int r = ar + p*64;
        int wm = r >> 6, w64 = r & 63;
        int mt = w64 >> 4, wi = w64 & 15;
        int gg = wi & 7, halfm = wi >> 3;
        a_st[p] = (unsigned)((wm*2 + aks)*A_BLK + (gg*4)*A_SLOT + mt*4 + (halfm + 2*ahalf));
        /* + tg*A_SLOT added per element */
    }
    /* ---- B store bases: krow -> (ks,tg2,c); bn -> (wn,nt,g0) ---- */
    int bwn = bn >> 5, bnt = (bn >> 3) & 3, bg0 = bn & 7;
    unsigned b_st[2];
    #pragma unroll
    for (int p = 0; p < 2; p++) {
        int krow = bk + p*8;
        int ks = krow >> 3, k8 = krow & 7;
        int tg2 = k8 & 3, cc = k8 >> 2;
        b_st[p] = (unsigned)((bwn*2 + ks)*B_BLK + (bg0*4 + tg2)*B_SLOT + cc*4 + bnt);
        /* + j*4*B_SLOT per element (g0+j) */
    }

    float acc[4][4][4];
    #pragma unroll
    for (int mt = 0; mt < 4; mt++)
        #pragma unroll
        for (int nt = 0; nt < 4; nt++)
            #pragma unroll
            for (int c = 0; c < 4; c++) acc[mt][nt][c] = 0.f;

    int nslab = K >> 4;
    float4 pa[2], pb[2];

    /* prologue: load slab 0, store to buffer 0 */
    {
        #pragma unroll
        for (int p = 0; p < 2; p++) {
            int r = row0 + ar + p*64;
            pa[p] = (r < M) ? *(const float4*)(A + (size_t)r*K + akq)
                            : make_float4(0.f,0.f,0.f,0.f);
            int kk = bk + p*8;
            pb[p] = *(const float4*)(Bm + (size_t)kk*N + col0 + bn);
        }
        #pragma unroll
        for (int p = 0; p < 2; p++) {
            unsigned* as = As[0];
            as[a_st[p] + 0*A_SLOT] = f2tf(pa[p].x);
            as[a_st[p] + 1*A_SLOT] = f2tf(pa[p].y);
            as[a_st[p] + 2*A_SLOT] = f2tf(pa[p].z);
            as[a_st[p] + 3*A_SLOT] = f2tf(pa[p].w);
            unsigned* bs = Bs[0];
            bs[b_st[p] + 0*4*B_SLOT] = f2tf(pb[p].x);
            bs[b_st[p] + 1*4*B_SLOT] = f2tf(pb[p].y);
            bs[b_st[p] + 2*4*B_SLOT] = f2tf(pb[p].z);
            bs[b_st[p] + 3*4*B_SLOT] = f2tf(pb[p].w);
        }
    }
    __syncthreads();

    for (int s = 0; s < nslab; s++) {
        int cur = s & 1;
        int nxt = cur ^ 1;
        int kt  = (s + 1) << 4;

        if (s + 1 < nslab) {
            #pragma unroll
            for (int p = 0; p < 2; p++) {
                int r = row0 + ar + p*64;
                pa[p] = (r < M) ? *(const float4*)(A + (size_t)r*K + kt + akq)
                                : make_float4(0.f,0.f,0.f,0.f);
                int kk = kt + bk + p*8;
                pb[p] = *(const float4*)(Bm + (size_t)kk*N + col0 + bn);
            }
        }

        /* compute current slab: 2 k8 steps, fragment LDS.128 */
        const unsigned* as = As[cur];
        const unsigned* bs = Bs[cur];
        unsigned aslot = (unsigned)((g*4 + tg)*A_SLOT);
        unsigned bslot = (unsigned)((g*4 + tg)*B_SLOT);
        #pragma unroll
        for (int ks = 0; ks < 2; ks++) {
            unsigned abase = (unsigned)((warp_m*2 + ks)*A_BLK) + aslot;
            unsigned bbase = (unsigned)((warp_n*2 + ks)*B_BLK) + bslot;
            unsigned af[4][4];
            #pragma unroll
            for (int mt = 0; mt < 4; mt++) {
                uint4 va = *(const uint4*)&as[abase + mt*4];
                af[mt][0] = va.x; af[mt][1] = va.y; af[mt][2] = va.z; af[mt][3] = va.w;
            }
            uint4 vb0 = *(const uint4*)&bs[bbase];      /* c0: nt0..3 */
            uint4 vb1 = *(const uint4*)&bs[bbase + 4];  /* c1: nt0..3 */
            unsigned bf[4][2];
            bf[0][0] = vb0.x; bf[0][1] = vb1.x;
            bf[1][0] = vb0.y; bf[1][1] = vb1.y;
            bf[2][0] = vb0.z; bf[2][1] = vb1.z;
            bf[3][0] = vb0.w; bf[3][1] = vb1.w;
            #pragma unroll
            for (int mt = 0; mt < 4; mt++)
                #pragma unroll
                for (int nt = 0; nt < 4; nt++)
                    mma_tf32(acc[mt][nt], af[mt][0], af[mt][1], af[mt][2], af[mt][3],
                             bf[nt][0], bf[nt][1]);
        }

        if (s + 1 < nslab) {
            #pragma unroll
            for (int p = 0; p < 2; p++) {
                unsigned* asn = As[nxt];
                asn[a_st[p] + 0*A_SLOT] = f2tf(pa[p].x);
                asn[a_st[p] + 1*A_SLOT] = f2tf(pa[p].y);
                asn[a_st[p] + 2*A_SLOT] = f2tf(pa[p].z);
                asn[a_st[p] + 3*A_SLOT] = f2tf(pa[p].w);
                unsigned* bsn = Bs[nxt];
                bsn[b_st[p] + 0*4*B_SLOT] = f2tf(pb[p].x);
                bsn[b_st[p] + 1*4*B_SLOT] = f2tf(pb[p].y);
                bsn[b_st[p] + 2*4*B_SLOT] = f2tf(pb[p].z);
                bsn[b_st[p] + 3*4*B_SLOT] = f2tf(pb[p].w);
            }
        }
        __syncthreads();
    }

    /* epilogue (unchanged layout): c0 (g, tg*2), c1 (g, tg*2+1), c2 (g+8, ..), c3 */
    #pragma unroll
    for (int mt = 0; mt < 4; mt++) {
        int gr0 = row0 + warp_m*64 + mt*16 + g;
        int gr1 = gr0 + 8;
        #pragma unroll
        for (int nt = 0; nt < 4; nt++) {
            int gc = col0 + warp_n*32 + nt*8 + tg*2;
            float bsv0 = bias[gc], bsv1 = bias[gc+1];
            if (gr0 < M) {
                float c0 = acc[mt][nt][0] + bsv0;
                float c1 = acc[mt][nt][1] + bsv1;
                if (RELU) { c0 = fmaxf(c0, 0.f); c1 = fmaxf(c1, 0.f); }
                C[(size_t)gr0*N + gc]     = c0;
                C[(size_t)gr0*N + gc + 1] = c1;
            }
            if (gr1 < M) {
                float c2 = acc[mt][nt][2] + bsv0;
                float c3 = acc[mt][nt][3] + bsv1;
                if (RELU) { c2 = fmaxf(c2, 0.f); c3 = fmaxf(c3, 0.f); }
                C[(size_t)gr1*N + gc]     = c2;
                C[(size_t)gr1*N + gc + 1] = c3;
            }
        }
    }
}

/* ------------------------- learned-mask projection (q & k merged) ------------------------ */
__global__ void lmproj_kernel(const float* __restrict__ q, const float* __restrict__ k,
                              const float* __restrict__ qw, const float* __restrict__ qb,
                              const float* __restrict__ kw, const float* __restrict__ kb2,
                              float* __restrict__ qp, float* __restrict__ kp) {
    __shared__ float row[DMODEL];
    int r = blockIdx.x;
    const float* src  = blockIdx.y ? k  : q;
    const float* w    = blockIdx.y ? kw : qw;
    const float* bias = blockIdx.y ? kb2: qb;
    float* out        = blockIdx.y ? kp : qp;
    int t = threadIdx.x;       /* 128 */
    row[t]       = src[(size_t)r*DMODEL + t];
    row[t+128]   = src[(size_t)r*DMODEL + t + 128];
    row[t+256]   = src[(size_t)r*DMODEL + t + 256];
    row[t+384]   = src[(size_t)r*DMODEL + t + 384];
    __syncthreads();
    int h = t >> 4, p = t & 15;
    float s = bias[p];
    #pragma unroll
    for (int d = 0; d < DK; d++) s += row[h*DK + d]*w[d*PDIM + p];
    out[(size_t)r*(HH*PDIM) + t] = s;
}

/* ------------------------- fused flash attention v2 (same as R5) ------------------------- */
#define FKP 84
#define FVP 72
#define FPP 84
#define SK_OFF 0
#define SV_OFF (2*64*FKP)
#define SP_OFF (SV_OFF + 2*64*FVP)
#define FLASH_SMEM_WORDS (SP_OFF + 128*FPP)
#define FLASH_SMEM_BYTES (FLASH_SMEM_WORDS*4)

__global__ __launch_bounds__(256) void flash_kernel(
    const float* __restrict__ q, const float* __restrict__ k,
    const float* __restrict__ v, const float* __restrict__ qp,
    const float* __restrict__ kp, float* __restrict__ ctx)
{
    extern __shared__ unsigned sm[];
    unsigned* sP = sm + SP_OFF;

    int tid  = threadIdx.x;
    int lane = tid & 31, wid = tid >> 5;
    int g = lane >> 2, tg = lane & 3;
    int m0 = wid * 16;
    int l0 = blockIdx.x * 128;
    int bh = blockIdx.y;
    int b = bh >> 3, h = bh & 7;

    unsigned smem_base = (unsigned)__cvta_generic_to_shared(sm);

    for (int idx = tid; idx < 128*80; idx += 256) {
        int r = idx / 80, d = idx - r*80;
        int l = l0 + r;
        float val = 0.f;
        if (l < LL) {
            if (d < 64) val = q[(size_t)(b*LL + l)*DMODEL + h*DK + d] * QKSCALE;
            else        val = qp[(size_t)(b*LL + l)*(HH*PDIM) + h*PDIM + (d - 64)];
        }
        sP[r*FPP + d] = f2tf(val);
    }
    __syncthreads();

    unsigned qf[10][4];
    #pragma unroll
    for (int kb8 = 0; kb8 < 10; kb8++) {
        int kb = kb8*8;
        qf[kb8][0] = sP[(m0 + g    )*FPP + kb + tg    ];
        qf[kb8][1] = sP[(m0 + g + 8)*FPP + kb + tg    ];
        qf[kb8][2] = sP[(m0 + g    )*FPP + kb + tg + 4];
        qf[kb8][3] = sP[(m0 + g + 8)*FPP + kb + tg + 4];
    }
    __syncthreads();

    float o[8][4];
    #pragma unroll
    for (int nt = 0; nt < 8; nt++)
        #pragma unroll
        for (int c = 0; c < 4; c++) o[nt][c] = 0.f;
    float mrow0 = -1e30f, mrow1 = -1e30f;
    float lrow0 = 0.f,    lrow1 = 0.f;

    auto load_tiles = [&](int it, int buf) {
        int s0 = it * 64;
        unsigned kb_addr = smem_base + (SK_OFF + buf*64*FKP)*4u;
        unsigned vb_addr = smem_base + (SV_OFF + buf*64*FVP)*4u;
        for (int c = tid; c < 64*20; c += 256) {
            int r = c / 20, cj = c - r*20;
            int s = s0 + r;
            int ok = (s < LL);
            int sc2 = ok ? s : (LL-1);
            const float* src;
            unsigned dw;
            if (cj < 16) {
                src = k + (size_t)(b*LL + sc2)*DMODEL + h*DK + cj*4;
                dw  = r*FKP + cj*4;
            } else {
                src = kp + (size_t)(b*LL + sc2)*(HH*PDIM) + h*PDIM + (cj-16)*4;
                dw  = r*FKP + 64 + (cj-16)*4;
            }
            cp16(kb_addr + dw*4u, src, ok ? 16 : 0);
        }
        for (int c = tid; c < 64*16; c += 256) {
            int r = c >> 4, cj = c & 15;
            int s = s0 + r;
            int ok = (s < LL);
            int sc2 = ok ? s : (LL-1);
            const float* src = v + (size_t)(b*LL + sc2)*DMODEL + h*DK + cj*4;
            cp16(vb_addr + (r*FVP + cj*4)*4u, src, ok ? 16 : 0);
        }
        asm volatile("cp.async.commit_group;" ::: "memory");
    };

    load_tiles(0, 0);

    for (int it = 0; it < 16; it++) {
        int cur = it & 1;
        if (it + 1 < 16) {
            load_tiles(it + 1, cur ^ 1);
            asm volatile("cp.async.wait_group 1;" ::: "memory");
        } else {
            asm volatile("cp.async.wait_group 0;" ::: "memory");
        }
        __syncthreads();

        const unsigned* bK = sm + SK_OFF + cur*64*FKP;
        const unsigned* bV = sm + SV_OFF + cur*64*FVP;
        int s0 = it * 64;

        float sc[8][4];

        #pragma unroll
        for (int nt = 0; nt < 8; nt++) {
            int n0 = nt*8;
            float c4[4] = {0.f, 0.f, 0.f, 0.f};
            #pragma unroll
            for (int kk = 8; kk < 10; kk++) {
                int kb = kk*8;
                unsigned b0 = bK[(n0 + g)*FKP + kb + tg    ];
                unsigned b1 = bK[(n0 + g)*FKP + kb + tg + 4];
                mma_tf32(c4, qf[kk][0], qf[kk][1], qf[kk][2], qf[kk][3], b0, b1);
            }
            sc[nt][0] = tanh_fast(c4[0]);
            sc[nt][1] = tanh_fast(c4[1]);
            sc[nt][2] = tanh_fast(c4[2]);
            sc[nt][3] = tanh_fast(c4[3]);
        }

        #pragma unroll
        for (int kb8 = 0; kb8 < 8; kb8++) {
            int kb = kb8*8;
            #pragma unroll
            for (int nt = 0; nt < 8; nt++) {
                int n0 = nt*8;
                unsigned b0 = bK[(n0 + g)*FKP + kb + tg    ];
                unsigned b1 = bK[(n0 + g)*FKP + kb + tg + 4];
                mma_tf32(sc[nt], qf[kb8][0], qf[kb8][1], qf[kb8][2], qf[kb8][3], b0, b1);
            }
        }

        if (s0 + 64 > LL) {
            #pragma unroll
            for (int nt = 0; nt < 8; nt++) {
                int col = s0 + nt*8 + 2*tg;
                if (col     >= LL) { sc[nt][0] = -1e30f; sc[nt][2] = -1e30f; }
                if (col + 1 >= LL) { sc[nt][1] = -1e30f; sc[nt][3] = -1e30f; }
            }
        }

        float mx0 = -1e30f, mx1 = -1e30f;
        #pragma unroll
        for (int nt = 0; nt < 8; nt++) {
            mx0 = fmaxf(mx0, fmaxf(sc[nt][0], sc[nt][1]));
            mx1 = fmaxf(mx1, fmaxf(sc[nt][2], sc[nt][3]));
        }
        #pragma unroll
        for (int off = 1; off <= 2; off <<= 1) {
            mx0 = fmaxf(mx0, __shfl_xor_sync(0xffffffffu, mx0, off));
            mx1 = fmaxf(mx1, __shfl_xor_sync(0xffffffffu, mx1, off));
        }
        float mn0 = fmaxf(mrow0, mx0), mn1 = fmaxf(mrow1, mx1);
        float corr0 = __expf(mrow0 - mn0), corr1 = __expf(mrow1 - mn1);
        mrow0 = mn0; mrow1 = mn1;

        float sum0 = 0.f, sum1 = 0.f;
        #pragma unroll
        for (int nt = 0; nt < 8; nt++) {
            float p0 = __expf(sc[nt][0] - mn0);
            float p1 = __expf(sc[nt][1] - mn0);
            float p2 = __expf(sc[nt][2] - mn1);
            float p3 = __expf(sc[nt][3] - mn1);
            sum0 += p0 + p1; sum1 += p2 + p3;
            uint2 w0; w0.x = f2tf(p0); w0.y = f2tf(p1);
            uint2 w1; w1.x = f2tf(p2); w1.y = f2tf(p3);
            *(uint2*)&sP[(m0 + g    )*FPP + nt*8 + 2*tg] = w0;
            *(uint2*)&sP[(m0 + g + 8)*FPP + nt*8 + 2*tg] = w1;
        }
        #pragma unroll
        for (int off = 1; off <= 2; off <<= 1) {
            sum0 += __shfl_xor_sync(0xffffffffu, sum0, off);
            sum1 += __shfl_xor_sync(0xffffffffu, sum1, off);
        }
        lrow0 = lrow0*corr0 + sum0;
        lrow1 = lrow1*corr1 + sum1;
        #pragma unroll
        for (int nt = 0; nt < 8; nt++) {
            o[nt][0] *= corr0; o[nt][1] *= corr0;
            o[nt][2] *= corr1; o[nt][3] *= corr1;
        }
        __syncwarp();

        #pragma unroll
        for (int kb8 = 0; kb8 < 8; kb8++) {
            int kb = kb8*8;
            unsigned a0 = sP[(m0 + g    )*FPP + kb + tg    ];
            unsigned a1 = sP[(m0 + g + 8)*FPP + kb + tg    ];
            unsigned a2 = sP[(m0 + g    )*FPP + kb + tg + 4];
            unsigned a3 = sP[(m0 + g + 8)*FPP + kb + tg + 4];
            #pragma unroll
            for (int nt = 0; nt < 8; nt++) {
                int n0 = nt*8;
                unsigned b0 = bV[(kb + tg    )*FVP + n0 + g];
                unsigned b1 = bV[(kb + tg + 4)*FVP + n0 + g];
                mma_tf32(o[nt], a0, a1, a2, a3, b0, b1);
            }
        }
        __syncthreads();
    }

    float inv0 = 1.f/lrow0, inv1 = 1.f/lrow1;
    int gl0 = l0 + m0 + g;
    int gl1 = gl0 + 8;
    #pragma unroll
    for (int nt = 0; nt < 8; nt++) {
        int d = h*DK + nt*8 + 2*tg;
        if (gl0 < LL) {
            float2 w; w.x = o[nt][0]*inv0; w.y = o[nt][1]*inv0;
            *(float2*)&ctx[(size_t)(b*LL + gl0)*DMODEL + d] = w;
        }
        if (gl1 < LL) {
            float2 w; w.x = o[nt][2]*inv1; w.y = o[nt][3]*inv1;
            *(float2*)&ctx[(size_t)(b*LL + gl1)*DMODEL + d] = w;
        }
    }
}

/* ------------------------- h = LN(h + res) ------------------------- */
__global__ void ln_residual_kernel(float* __restrict__ h, const float* __restrict__ res,
                                   const float* __restrict__ g, const float* __restrict__ b) {
    __shared__ float sbuf[32];
    int r = blockIdx.x, t = threadIdx.x;
    size_t base = (size_t)r*DMODEL;
    float v0 = h[base + t]       + res[base + t];
    float v1 = h[base + t + 256] + res[base + t + 256];
    float mean = block_reduce_sum(v0 + v1, sbuf) * (1.f/DMODEL);
    float d0 = v0 - mean, d1 = v1 - mean;
    float var = block_reduce_sum(d0*d0 + d1*d1, sbuf) * (1.f/DMODEL);
    float inv = rsqrtf(var + LEPS);
    h[base + t]       = d0*inv*g[t]     + b[t];
    h[base + t + 256] = d1*inv*g[t+256] + b[t+256];
}

/* ------------------------- h = LN(LN(h+y)+y) ------------------------- */
__global__ void double_ln_kernel(float* __restrict__ h, const float* __restrict__ y,
                                 const float* __restrict__ g, const float* __restrict__ b) {
    __shared__ float sbuf[32];
    int r = blockIdx.x, t = threadIdx.x;
    size_t base = (size_t)r*DMODEL;
    float y0 = y[base + t], y1 = y[base + t + 256];
    float t0 = h[base + t] + y0, t1 = h[base + t + 256] + y1;
    float mean = block_reduce_sum(t0 + t1, sbuf) * (1.f/DMODEL);
    float d0 = t0 - mean, d1 = t1 - mean;
    float var = block_reduce_sum(d0*d0 + d1*d1, sbuf) * (1.f/DMODEL);
    float inv = rsqrtf(var + LEPS);
    float h20 = d0*inv*g[t]     + b[t];
    float h21 = d1*inv*g[t+256] + b[t+256];
    float u0 = h20 + y0, u1 = h21 + y1;
    mean = block_reduce_sum(u0 + u1, sbuf) * (1.f/DMODEL);
    d0 = u0 - mean; d1 = u1 - mean;
    var = block_reduce_sum(d0*d0 + d1*d1, sbuf) * (1.f/DMODEL);
    inv = rsqrtf(var + LEPS);
    h[base + t]       = d0*inv*g[t]     + b[t];
    h[base + t + 256] = d1*inv*g[t+256] + b[t+256];
}

/* ------------------------- final: LN(last token) @ fc_w + fc_b ------------------------- */
__global__ void final_kernel(const float* __restrict__ h, const float* __restrict__ gn,
                             const float* __restrict__ bn, const float* __restrict__ fw,
                             const float* __restrict__ fb, float* __restrict__ out) {
    __shared__ float sbuf[32];
    __shared__ float row[DMODEL];
    int b = blockIdx.x, t = threadIdx.x;
    const float* hr = h + (size_t)(b*LL + (LL-1))*DMODEL;
    float v0 = hr[t], v1 = hr[t + 256];
    float mean = block_reduce_sum(v0 + v1, sbuf) * (1.f/DMODEL);
    float d0 = v0 - mean, d1 = v1 - mean;
    float var = block_reduce_sum(d0*d0 + d1*d1, sbuf) * (1.f/DMODEL);
    float inv = rsqrtf(var + LEPS);
    row[t]       = d0*inv*gn[t]     + bn[t];
    row[t + 256] = d1*inv*gn[t+256] + bn[t+256];
    __syncthreads();
    for (int p = t; p < NPRED; p += 256) {
        float s = fb[p];
        for (int d = 0; d < DMODEL; d++) s += row[d]*fw[(size_t)d*NPRED + p];
        out[(size_t)b*NPRED + p] = s;
    }
}

/* ------------------------- launch ------------------------- */
extern "C" void kernel_launch(void* const* d_in, const int* in_sizes, int n_in,
                              void* d_out, int out_size) {
    const float* x     = (const float*)d_in[0];
    const float* emb_w = (const float*)d_in[1];
    const float* emb_b = (const float*)d_in[2];
    const float* pe    = (const float*)d_in[3];
    const float* Wq    = (const float*)d_in[4];
    const float* bq    = (const float*)d_in[5];
    const float* Wk    = (const float*)d_in[6];
    const float* bk    = (const float*)d_in[7];
    const float* Wv    = (const float*)d_in[8];
    const float* bv    = (const float*)d_in[9];
    const float* Wo    = (const float*)d_in[10];
    const float* bo    = (const float*)d_in[11];
    const float* W1    = (const float*)d_in[12];
    const float* b1    = (const float*)d_in[13];
    const float* W2    = (const float*)d_in[14];
    const float* b2    = (const float*)d_in[15];
    const float* g1    = (const float*)d_in[16];
    const float* be1   = (const float*)d_in[17];
    const float* g2    = (const float*)d_in[18];
    const float* be2   = (const float*)d_in[19];
    const float* lm_qw = (const float*)d_in[20];
    const float* lm_qb = (const float*)d_in[21];
    const float* lm_kw = (const float*)d_in[22];
    const float* lm_kb = (const float*)d_in[23];
    const float* gn    = (const float*)d_in[24];
    const float* bn    = (const float*)d_in[25];
    const float* fc_w  = (const float*)d_in[26];
    const float* fc_b  = (const float*)d_in[27];
    float* out = (float*)d_out;

    float *h, *q, *k, *v, *ctx, *y, *qp, *kp, *ffn;
    cudaGetSymbolAddress((void**)&h,   g_h);
    cudaGetSymbolAddress((void**)&q,   g_q);
    cudaGetSymbolAddress((void**)&k,   g_k);
    cudaGetSymbolAddress((void**)&v,   g_v);
    cudaGetSymbolAddress((void**)&ctx, g_ctx);
    cudaGetSymbolAddress((void**)&y,   g_y);
    cudaGetSymbolAddress((void**)&qp,  g_qp);
    cudaGetSymbolAddress((void**)&kp,  g_kp);
    cudaGetSymbolAddress((void**)&ffn, g_ffn);

    cudaFuncSetAttribute(flash_kernel,
                         cudaFuncAttributeMaxDynamicSharedMemorySize, FLASH_SMEM_BYTES);

    embed_kernel<<<ROWS, 256>>>(x, emb_w, emb_b, pe, h);

    dim3 g512(DMODEL/128, (ROWS + 127)/128);
    dim3 gff (DFF/128,    (ROWS + 127)/128);
    dim3 gfl (8, BB*HH);
    dim3 glm (ROWS, 2);

    for (int i = 0; i < NLAYERS; i++) {
        const float* Wq_i = Wq + (size_t)i*DMODEL*DMODEL;
        const float* Wk_i = Wk + (size_t)i*DMODEL*DMODEL;
        const float* Wv_i = Wv + (size_t)i*DMODEL*DMODEL;
        const float* Wo_i = Wo + (size_t)i*DMODEL*DMODEL;
        const float* bq_i = bq + (size_t)i*DMODEL;
        const float* bk_i = bk + (size_t)i*DMODEL;
        const float* bv_i = bv + (size_t)i*DMODEL;
        const float* bo_i = bo + (size_t)i*DMODEL;
        const float* W1_i = W1 + (size_t)i*DMODEL*DFF;
        const float* b1_i = b1 + (size_t)i*DFF;
        const float* W2_i = W2 + (size_t)i*DFF*DMODEL;
        const float* b2_i = b2 + (size_t)i*DMODEL;
        const float* g1_i = g1 + (size_t)i*DMODEL;
        const float* be1_i= be1+ (size_t)i*DMODEL;
        const float* g2_i = g2 + (size_t)i*DMODEL;
        const float* be2_i= be2+ (size_t)i*DMODEL;

        gemm_tf32<0><<<g512, 256>>>(h, Wq_i, bq_i, q, ROWS, DMODEL, DMODEL);
        gemm_tf32<0><<<g512, 256>>>(h, Wk_i, bk_i, k, ROWS, DMODEL, DMODEL);
        gemm_tf32<0><<<g512, 256>>>(h, Wv_i, bv_i, v, ROWS, DMODEL, DMODEL);

        lmproj_kernel<<<glm, 128>>>(q, k, lm_qw, lm_qb, lm_kw, lm_kb, qp, kp);

        flash_kernel<<<gfl, 256, FLASH_SMEM_BYTES>>>(q, k, v, qp, kp, ctx);

        gemm_tf32<0><<<g512, 256>>>(ctx, Wo_i, bo_i, q, ROWS, DMODEL, DMODEL);
        ln_residual_kernel<<<ROWS, 256>>>(h, q, g1_i, be1_i);

        gemm_tf32<1><<<gff, 256>>>(h, W1_i, b1_i, ffn, ROWS, DFF, DMODEL);
        gemm_tf32<0><<<g512, 256>>>(ffn, W2_i, b2_i, y, ROWS, DMODEL, DFF);
        double_ln_kernel<<<ROWS, 256>>>(h, y, g2_i, be2_i);
    }

    final_kernel<<<BB, 256>>>(h, gn, bn, fc_w, fc_b, out);
    (void)in_sizes; (void)n_in; (void)out_size;
}

// round 9
// speedup vs baseline: 1.7927x; 1.0719x over previous
#include <cuda_runtime.h>
#include <math.h>

#define BB 8
#define LL 1000
#define DMODEL 512
#define HH 8
#define DK 64
#define PDIM 16
#define DFF 2048
#define NLAYERS 4
#define NPRED 50
#define ROWS (BB*LL)            /* 8000 */
#define LEPS 1e-5f
#define QKSCALE 0.125f          /* 1/sqrt(64) */

/* ------------------------- scratch (device globals; no allocs) ------------------------- */
__device__ float g_h   [ROWS*DMODEL];
__device__ float g_hr  [ROWS*DMODEL];          /* rna-rounded copy of h (GEMM A) */
__device__ float g_q   [ROWS*DMODEL];
__device__ float g_k   [ROWS*DMODEL];
__device__ float g_v   [ROWS*DMODEL];
__device__ float g_ctx [ROWS*DMODEL];          /* rounded at producer (flash) */
__device__ float g_y   [ROWS*DMODEL];
__device__ float g_qp  [ROWS*HH*PDIM];
__device__ float g_kp  [ROWS*HH*PDIM];
__device__ float g_ffn [ROWS*DFF];             /* rounded at producer (FFN1 epilogue) */
/* rna-rounded weights */
__device__ float g_wqr [NLAYERS*DMODEL*DMODEL];
__device__ float g_wkr [NLAYERS*DMODEL*DMODEL];
__device__ float g_wvr [NLAYERS*DMODEL*DMODEL];
__device__ float g_wor [NLAYERS*DMODEL*DMODEL];
__device__ float g_w1r [NLAYERS*DMODEL*DFF];
__device__ float g_w2r [NLAYERS*DFF*DMODEL];

/* ------------------------- reductions ------------------------- */
__device__ __forceinline__ float block_reduce_sum(float v, float* sbuf) {
    int t = threadIdx.x;
    #pragma unroll
    for (int o = 16; o > 0; o >>= 1) v += __shfl_xor_sync(0xffffffffu, v, o);
    if ((t & 31) == 0) sbuf[t >> 5] = v;
    __syncthreads();
    if (t < 32) {
        float w = (t < (int)(blockDim.x >> 5)) ? sbuf[t] : 0.f;
        #pragma unroll
        for (int o = 16; o > 0; o >>= 1) w += __shfl_xor_sync(0xffffffffu, w, o);
        if (t == 0) sbuf[0] = w;
    }
    __syncthreads();
    float r = sbuf[0];
    __syncthreads();
    return r;
}

/* ------------------------- tf32 helpers ------------------------- */
__device__ __forceinline__ unsigned f2tf(float x) {
    unsigned r;
    asm("cvt.rna.tf32.f32 %0, %1;" : "=r"(r) : "f"(x));
    return r;
}
__device__ __forceinline__ float roundtf(float x) { return __uint_as_float(f2tf(x)); }

__device__ __forceinline__ void mma_tf32(float c[4], unsigned a0, unsigned a1,
                                         unsigned a2, unsigned a3,
                                         unsigned b0, unsigned b1) {
    asm volatile(
        "mma.sync.aligned.m16n8k8.row.col.f32.tf32.tf32.f32 "
        "{%0,%1,%2,%3}, {%4,%5,%6,%7}, {%8,%9}, {%0,%1,%2,%3};\n"
        : "+f"(c[0]), "+f"(c[1]), "+f"(c[2]), "+f"(c[3])
        : "r"(a0), "r"(a1), "r"(a2), "r"(a3), "r"(b0), "r"(b1));
}

__device__ __forceinline__ float tanh_fast(float x) {
    float e = __expf(2.f*x);
    return 1.f - 2.f/(e + 1.f);
}

__device__ __forceinline__ void cp16(unsigned dst_smem, const void* src, int src_bytes) {
    asm volatile("cp.async.cg.shared.global [%0], [%1], 16, %2;"
                 :: "r"(dst_smem), "l"(src), "r"(src_bytes));
}

/* ------------------------- weight rounding (once per launch) ------------------------- */
__global__ void round_kernel(const float4* __restrict__ in, float4* __restrict__ out, int n4) {
    int stride = gridDim.x * blockDim.x;
    for (int i = blockIdx.x*blockDim.x + threadIdx.x; i < n4; i += stride) {
        float4 v = in[i];
        v.x = roundtf(v.x); v.y = roundtf(v.y);
        v.z = roundtf(v.z); v.w = roundtf(v.w);
        out[i] = v;
    }
}

/* ------------------------- embedding: h = x @ emb_w + emb_b + pe ------------------------- */
__global__ void embed_kernel(const float* __restrict__ x, const float* __restrict__ ew,
                             const float* __restrict__ eb, const float* __restrict__ pe,
                             float* __restrict__ h, float* __restrict__ hr) {
    int r = blockIdx.x;
    int t = threadIdx.x;
    __shared__ float xs[7];
    if (t < 7) xs[t] = x[(size_t)r*7 + t];
    __syncthreads();
    int l = r % LL;
    for (int d = t; d < DMODEL; d += 256) {
        float s = eb[d] + pe[(size_t)l*DMODEL + d];
        #pragma unroll
        for (int f = 0; f < 7; f++) s += xs[f]*ew[(size_t)f*DMODEL + d];
        h [(size_t)r*DMODEL + d] = s;
        hr[(size_t)r*DMODEL + d] = roundtf(s);
    }
}

/* ------------------------- tf32 GEMM v4: cp.async 3-stage, pre-rounded inputs ------------
   C[M,N] = A[M,K] @ B[K,N] + bias, opt ReLU, opt ROUND(output -> rna tf32 bits).
   A and B must already be rna-rounded; cp.async truncation is then the identity.
   BM=BN=128, BK=16, 256 threads. N%128==0, K%16==0; M guarded via zfill.              */
#define APITCH 20
#define BPITCH 136
#define GSTAGES 3
template<int RELU, int ROUND>
__global__ __launch_bounds__(256, 2) void gemm_tf32(const float* __restrict__ A,
                                                    const float* __restrict__ Bm,
                                                    const float* __restrict__ bias,
                                                    float* __restrict__ C,
                                                    int M, int N, int K) {
    __shared__ unsigned As[GSTAGES][128*APITCH];
    __shared__ unsigned Bs[GSTAGES][16*BPITCH];

    int tid  = threadIdx.x;
    int lane = tid & 31;
    int wid  = tid >> 5;
    int g    = lane >> 2;
    int tg   = lane & 3;
    int warp_m = wid & 1;
    int warp_n = wid >> 1;

    int row0 = blockIdx.y * 128;
    int col0 = blockIdx.x * 128;

    int ar  = tid >> 2;           /* 0..63 */
    int akq = (tid & 3) * 4;
    int bk  = tid >> 5;           /* 0..7 */
    int bn  = (tid & 31) * 4;

    int r0c = row0 + ar,      ok0 = (r0c < M);  if (!ok0) r0c = M-1;
    int r1c = row0 + ar + 64, ok1 = (r1c < M);  if (!ok1) r1c = M-1;
    const float* arow0 = A + (size_t)r0c*K + akq;
    const float* arow1 = A + (size_t)r1c*K + akq;
    const float* brow0 = Bm + (size_t)bk*N + col0 + bn;
    const float* brow1 = Bm + (size_t)(bk+8)*N + col0 + bn;

    unsigned sa_base = (unsigned)__cvta_generic_to_shared(&As[0][0]);
    unsigned sb_base = (unsigned)__cvta_generic_to_shared(&Bs[0][0]);
    unsigned sa0 = (ar     )*APITCH + akq;
    unsigned sa1 = (ar + 64)*APITCH + akq;
    unsigned sb0 = (bk     )*BPITCH + bn;
    unsigned sb1 = (bk +  8)*BPITCH + bn;

    int nslab = K >> 4;

    auto load_slab = [&](int s, int buf) {
        int kt = s << 4;
        unsigned ab = sa_base + (unsigned)buf*(128*APITCH*4u);
        unsigned bb = sb_base + (unsigned)buf*(16*BPITCH*4u);
        cp16(ab + sa0*4u, arow0 + kt, ok0 ? 16 : 0);
        cp16(ab + sa1*4u, arow1 + kt, ok1 ? 16 : 0);
        cp16(bb + sb0*4u, brow0 + (size_t)kt*N, 16);
        cp16(bb + sb1*4u, brow1 + (size_t)kt*N, 16);
        asm volatile("cp.async.commit_group;" ::: "memory");
    };

    float acc[4][4][4];
    #pragma unroll
    for (int mt = 0; mt < 4; mt++)
        #pragma unroll
        for (int nt = 0; nt < 4; nt++)
            #pragma unroll
            for (int c = 0; c < 4; c++) acc[mt][nt][c] = 0.f;

    #pragma unroll
    for (int s = 0; s < GSTAGES-1; s++)
        if (s < nslab) load_slab(s, s);

    for (int s = 0; s < nslab; s++) {
        int cur = s % GSTAGES;
        asm volatile("cp.async.wait_group %0;" :: "n"(GSTAGES-2) : "memory");
        __syncthreads();

        int nidx = s + GSTAGES - 1;
        if (nidx < nslab) load_slab(nidx, nidx % GSTAGES);

        const unsigned* as = As[cur];
        const unsigned* bs = Bs[cur];

        #pragma unroll
        for (int ks = 0; ks < 2; ks++) {
            int kb = ks * 8;
            unsigned af[4][4];
            #pragma unroll
            for (int mt = 0; mt < 4; mt++) {
                int m0 = warp_m*64 + mt*16;
                af[mt][0] = as[(m0 + g    )*APITCH + kb + tg    ];
                af[mt][1] = as[(m0 + g + 8)*APITCH + kb + tg    ];
                af[mt][2] = as[(m0 + g    )*APITCH + kb + tg + 4];
                af[mt][3] = as[(m0 + g + 8)*APITCH + kb + tg + 4];
            }
            unsigned bf[4][2];
            #pragma unroll
            for (int nt = 0; nt < 4; nt++) {
                int n0 = warp_n*32 + nt*8;
                bf[nt][0] = bs[(kb + tg    )*BPITCH + n0 + g];
                bf[nt][1] = bs[(kb + tg + 4)*BPITCH + n0 + g];
            }
            #pragma unroll
            for (int mt = 0; mt < 4; mt++)
                #pragma unroll
                for (int nt = 0; nt < 4; nt++)
                    mma_tf32(acc[mt][nt], af[mt][0], af[mt][1], af[mt][2], af[mt][3],
                             bf[nt][0], bf[nt][1]);
        }
        __syncthreads();
    }

    #pragma unroll
    for (int mt = 0; mt < 4; mt++) {
        int gr0 = row0 + warp_m*64 + mt*16 + g;
        int gr1 = gr0 + 8;
        #pragma unroll
        for (int nt = 0; nt < 4; nt++) {
            int gc = col0 + warp_n*32 + nt*8 + tg*2;
            float bsv0 = bias[gc], bsv1 = bias[gc+1];
            if (gr0 < M) {
                float c0 = acc[mt][nt][0] + bsv0;
                float c1 = acc[mt][nt][1] + bsv1;
                if (RELU) { c0 = fmaxf(c0, 0.f); c1 = fmaxf(c1, 0.f); }
                if (ROUND) { c0 = roundtf(c0); c1 = roundtf(c1); }
                C[(size_t)gr0*N + gc]     = c0;
                C[(size_t)gr0*N + gc + 1] = c1;
            }
            if (gr1 < M) {
                float c2 = acc[mt][nt][2] + bsv0;
                float c3 = acc[mt][nt][3] + bsv1;
                if (RELU) { c2 = fmaxf(c2, 0.f); c3 = fmaxf(c3, 0.f); }
                if (ROUND) { c2 = roundtf(c2); c3 = roundtf(c3); }
                C[(size_t)gr1*N + gc]     = c2;
                C[(size_t)gr1*N + gc + 1] = c3;
            }
        }
    }
}

/* ------------------------- learned-mask projection (q & k merged) ------------------------ */
__global__ void lmproj_kernel(const float* __restrict__ q, const float* __restrict__ k,
                              const float* __restrict__ qw, const float* __restrict__ qb,
                              const float* __restrict__ kw, const float* __restrict__ kb2,
                              float* __restrict__ qp, float* __restrict__ kp) {
    __shared__ float row[DMODEL];
    int r = blockIdx.x;
    const float* src  = blockIdx.y ? k  : q;
    const float* w    = blockIdx.y ? kw : qw;
    const float* bias = blockIdx.y ? kb2: qb;
    float* out        = blockIdx.y ? kp : qp;
    int t = threadIdx.x;       /* 128 */
    row[t]       = src[(size_t)r*DMODEL + t];
    row[t+128]   = src[(size_t)r*DMODEL + t + 128];
    row[t+256]   = src[(size_t)r*DMODEL + t + 256];
    row[t+384]   = src[(size_t)r*DMODEL + t + 384];
    __syncthreads();
    int h = t >> 4, p = t & 15;
    float s = bias[p];
    #pragma unroll
    for (int d = 0; d < DK; d++) s += row[h*DK + d]*w[d*PDIM + p];
    out[(size_t)r*(HH*PDIM) + t] = s;
}

/* ------------------------- fused flash attention v2 (ctx rounded at write) --------------- */
#define FKP 84
#define FVP 72
#define FPP 84
#define SK_OFF 0
#define SV_OFF (2*64*FKP)
#define SP_OFF (SV_OFF + 2*64*FVP)
#define FLASH_SMEM_WORDS (SP_OFF + 128*FPP)
#define FLASH_SMEM_BYTES (FLASH_SMEM_WORDS*4)

__global__ __launch_bounds__(256) void flash_kernel(
    const float* __restrict__ q, const float* __restrict__ k,
    const float* __restrict__ v, const float* __restrict__ qp,
    const float* __restrict__ kp, float* __restrict__ ctx)
{
    extern __shared__ unsigned sm[];
    unsigned* sP = sm + SP_OFF;

    int tid  = threadIdx.x;
    int lane = tid & 31, wid = tid >> 5;
    int g = lane >> 2, tg = lane & 3;
    int m0 = wid * 16;
    int l0 = blockIdx.x * 128;
    int bh = blockIdx.y;
    int b = bh >> 3, h = bh & 7;

    unsigned smem_base = (unsigned)__cvta_generic_to_shared(sm);

    for (int idx = tid; idx < 128*80; idx += 256) {
        int r = idx / 80, d = idx - r*80;
        int l = l0 + r;
        float val = 0.f;
        if (l < LL) {
            if (d < 64) val = q[(size_t)(b*LL + l)*DMODEL + h*DK + d] * QKSCALE;
            else        val = qp[(size_t)(b*LL + l)*(HH*PDIM) + h*PDIM + (d - 64)];
        }
        sP[r*FPP + d] = f2tf(val);
    }
    __syncthreads();

    unsigned qf[10][4];
    #pragma unroll
    for (int kb8 = 0; kb8 < 10; kb8++) {
        int kb = kb8*8;
        qf[kb8][0] = sP[(m0 + g    )*FPP + kb + tg    ];
        qf[kb8][1] = sP[(m0 + g + 8)*FPP + kb + tg    ];
        qf[kb8][2] = sP[(m0 + g    )*FPP + kb + tg + 4];
        qf[kb8][3] = sP[(m0 + g + 8)*FPP + kb + tg + 4];
    }
    __syncthreads();

    float o[8][4];
    #pragma unroll
    for (int nt = 0; nt < 8; nt++)
        #pragma unroll
        for (int c = 0; c < 4; c++) o[nt][c] = 0.f;
    float mrow0 = -1e30f, mrow1 = -1e30f;
    float lrow0 = 0.f,    lrow1 = 0.f;

    auto load_tiles = [&](int it, int buf) {
        int s0 = it * 64;
        unsigned kb_addr = smem_base + (SK_OFF + buf*64*FKP)*4u;
        unsigned vb_addr = smem_base + (SV_OFF + buf*64*FVP)*4u;
        for (int c = tid; c < 64*20; c += 256) {
            int r = c / 20, cj = c - r*20;
            int s = s0 + r;
            int ok = (s < LL);
            int sc2 = ok ? s : (LL-1);
            const float* src;
            unsigned dw;
            if (cj < 16) {
                src = k + (size_t)(b*LL + sc2)*DMODEL + h*DK + cj*4;
                dw  = r*FKP + cj*4;
            } else {
                src = kp + (size_t)(b*LL + sc2)*(HH*PDIM) + h*PDIM + (cj-16)*4;
                dw  = r*FKP + 64 + (cj-16)*4;
            }
            cp16(kb_addr + dw*4u, src, ok ? 16 : 0);
        }
        for (int c = tid; c < 64*16; c += 256) {
            int r = c >> 4, cj = c & 15;
            int s = s0 + r;
            int ok = (s < LL);
            int sc2 = ok ? s : (LL-1);
            const float* src = v + (size_t)(b*LL + sc2)*DMODEL + h*DK + cj*4;
            cp16(vb_addr + (r*FVP + cj*4)*4u, src, ok ? 16 : 0);
        }
        asm volatile("cp.async.commit_group;" ::: "memory");
    };

    load_tiles(0, 0);

    for (int it = 0; it < 16; it++) {
        int cur = it & 1;
        if (it + 1 < 16) {
            load_tiles(it + 1, cur ^ 1);
            asm volatile("cp.async.wait_group 1;" ::: "memory");
        } else {
            asm volatile("cp.async.wait_group 0;" ::: "memory");
        }
        __syncthreads();

        const unsigned* bK = sm + SK_OFF + cur*64*FKP;
        const unsigned* bV = sm + SV_OFF + cur*64*FVP;
        int s0 = it * 64;

        float sc[8][4];

        #pragma unroll
        for (int nt = 0; nt < 8; nt++) {
            int n0 = nt*8;
            float c4[4] = {0.f, 0.f, 0.f, 0.f};
            #pragma unroll
            for (int kk = 8; kk < 10; kk++) {
                int kb = kk*8;
                unsigned b0 = bK[(n0 + g)*FKP + kb + tg    ];
                unsigned b1 = bK[(n0 + g)*FKP + kb + tg + 4];
                mma_tf32(c4, qf[kk][0], qf[kk][1], qf[kk][2], qf[kk][3], b0, b1);
            }
            sc[nt][0] = tanh_fast(c4[0]);
            sc[nt][1] = tanh_fast(c4[1]);
            sc[nt][2] = tanh_fast(c4[2]);
            sc[nt][3] = tanh_fast(c4[3]);
        }

        #pragma unroll
        for (int kb8 = 0; kb8 < 8; kb8++) {
            int kb = kb8*8;
            #pragma unroll
            for (int nt = 0; nt < 8; nt++) {
                int n0 = nt*8;
                unsigned b0 = bK[(n0 + g)*FKP + kb + tg    ];
                unsigned b1 = bK[(n0 + g)*FKP + kb + tg + 4];
                mma_tf32(sc[nt], qf[kb8][0], qf[kb8][1], qf[kb8][2], qf[kb8][3], b0, b1);
            }
        }

        if (s0 + 64 > LL) {
            #pragma unroll
            for (int nt = 0; nt < 8; nt++) {
                int col = s0 + nt*8 + 2*tg;
                if (col     >= LL) { sc[nt][0] = -1e30f; sc[nt][2] = -1e30f; }
                if (col + 1 >= LL) { sc[nt][1] = -1e30f; sc[nt][3] = -1e30f; }
            }
        }

        float mx0 = -1e30f, mx1 = -1e30f;
        #pragma unroll
        for (int nt = 0; nt < 8; nt++) {
            mx0 = fmaxf(mx0, fmaxf(sc[nt][0], sc[nt][1]));
            mx1 = fmaxf(mx1, fmaxf(sc[nt][2], sc[nt][3]));
        }
        #pragma unroll
        for (int off = 1; off <= 2; off <<= 1) {
            mx0 = fmaxf(mx0, __shfl_xor_sync(0xffffffffu, mx0, off));
            mx1 = fmaxf(mx1, __shfl_xor_sync(0xffffffffu, mx1, off));
        }
        float mn0 = fmaxf(mrow0, mx0), mn1 = fmaxf(mrow1, mx1);
        float corr0 = __expf(mrow0 - mn0), corr1 = __expf(mrow1 - mn1);
        mrow0 = mn0; mrow1 = mn1;

        float sum0 = 0.f, sum1 = 0.f;
        #pragma unroll
        for (int nt = 0; nt < 8; nt++) {
            float p0 = __expf(sc[nt][0] - mn0);
            float p1 = __expf(sc[nt][1] - mn0);
            float p2 = __expf(sc[nt][2] - mn1);
            float p3 = __expf(sc[nt][3] - mn1);
            sum0 += p0 + p1; sum1 += p2 + p3;
            uint2 w0; w0.x = f2tf(p0); w0.y = f2tf(p1);
            uint2 w1; w1.x = f2tf(p2); w1.y = f2tf(p3);
            *(uint2*)&sP[(m0 + g    )*FPP + nt*8 + 2*tg] = w0;
            *(uint2*)&sP[(m0 + g + 8)*FPP + nt*8 + 2*tg] = w1;
        }
        #pragma unroll
        for (int off = 1; off <= 2; off <<= 1) {
            sum0 += __shfl_xor_sync(0xffffffffu, sum0, off);
            sum1 += __shfl_xor_sync(0xffffffffu, sum1, off);
        }
        lrow0 = lrow0*corr0 + sum0;
        lrow1 = lrow1*corr1 + sum1;
        #pragma unroll
        for (int nt = 0; nt < 8; nt++) {
            o[nt][0] *= corr0; o[nt][1] *= corr0;
            o[nt][2] *= corr1; o[nt][3] *= corr1;
        }
        __syncwarp();

        #pragma unroll
        for (int kb8 = 0; kb8 < 8; kb8++) {
            int kb = kb8*8;
            unsigned a0 = sP[(m0 + g    )*FPP + kb + tg    ];
            unsigned a1 = sP[(m0 + g + 8)*FPP + kb + tg    ];
            unsigned a2 = sP[(m0 + g    )*FPP + kb + tg + 4];
            unsigned a3 = sP[(m0 + g + 8)*FPP + kb + tg + 4];
            #pragma unroll
            for (int nt = 0; nt < 8; nt++) {
                int n0 = nt*8;
                unsigned b0 = bV[(kb + tg    )*FVP + n0 + g];
                unsigned b1 = bV[(kb + tg + 4)*FVP + n0 + g];
                mma_tf32(o[nt], a0, a1, a2, a3, b0, b1);
            }
        }
        __syncthreads();
    }

    /* epilogue: O /= l, rna-round (ctx feeds only the O-projection GEMM) */
    float inv0 = 1.f/lrow0, inv1 = 1.f/lrow1;
    int gl0 = l0 + m0 + g;
    int gl1 = gl0 + 8;
    #pragma unroll
    for (int nt = 0; nt < 8; nt++) {
        int d = h*DK + nt*8 + 2*tg;
        if (gl0 < LL) {
            float2 w; w.x = roundtf(o[nt][0]*inv0); w.y = roundtf(o[nt][1]*inv0);
            *(float2*)&ctx[(size_t)(b*LL + gl0)*DMODEL + d] = w;
        }
        if (gl1 < LL) {
            float2 w; w.x = roundtf(o[nt][2]*inv1); w.y = roundtf(o[nt][3]*inv1);
            *(float2*)&ctx[(size_t)(b*LL + gl1)*DMODEL + d] = w;
        }
    }
}

/* ------------------------- h = LN(h + res), plus rounded copy ------------------------- */
__global__ void ln_residual_kernel(float* __restrict__ h, float* __restrict__ hr,
                                   const float* __restrict__ res,
                                   const float* __restrict__ g, const float* __restrict__ b) {
    __shared__ float sbuf[32];
    int r = blockIdx.x, t = threadIdx.x;
    size_t base = (size_t)r*DMODEL;
    float v0 = h[base + t]       + res[base + t];
    float v1 = h[base + t + 256] + res[base + t + 256];
    float mean = block_reduce_sum(v0 + v1, sbuf) * (1.f/DMODEL);
    float d0 = v0 - mean, d1 = v1 - mean;
    float var = block_reduce_sum(d0*d0 + d1*d1, sbuf) * (1.f/DMODEL);
    float inv = rsqrtf(var + LEPS);
    float o0 = d0*inv*g[t]     + b[t];
    float o1 = d1*inv*g[t+256] + b[t+256];
    h [base + t]       = o0;
    h [base + t + 256] = o1;
    hr[base + t]       = roundtf(o0);
    hr[base + t + 256] = roundtf(o1);
}

/* ------------------------- h = LN(LN(h+y)+y), plus rounded copy ------------------------- */
__global__ void double_ln_kernel(float* __restrict__ h, float* __restrict__ hr,
                                 const float* __restrict__ y,
                                 const float* __restrict__ g, const float* __restrict__ b) {
    __shared__ float sbuf[32];
    int r = blockIdx.x, t = threadIdx.x;
    size_t base = (size_t)r*DMODEL;
    float y0 = y[base + t], y1 = y[base + t + 256];
    float t0 = h[base + t] + y0, t1 = h[base + t + 256] + y1;
    float mean = block_reduce_sum(t0 + t1, sbuf) * (1.f/DMODEL);
    float d0 = t0 - mean, d1 = t1 - mean;
    float var = block_reduce_sum(d0*d0 + d1*d1, sbuf) * (1.f/DMODEL);
    float inv = rsqrtf(var + LEPS);
    float h20 = d0*inv*g[t]     + b[t];
    float h21 = d1*inv*g[t+256] + b[t+256];
    float u0 = h20 + y0, u1 = h21 + y1;
    mean = block_reduce_sum(u0 + u1, sbuf) * (1.f/DMODEL);
    d0 = u0 - mean; d1 = u1 - mean;
    var = block_reduce_sum(d0*d0 + d1*d1, sbuf) * (1.f/DMODEL);
    inv = rsqrtf(var + LEPS);
    float o0 = d0*inv*g[t]     + b[t];
    float o1 = d1*inv*g[t+256] + b[t+256];
    h [base + t]       = o0;
    h [base + t + 256] = o1;
    hr[base + t]       = roundtf(o0);
    hr[base + t + 256] = roundtf(o1);
}

/* ------------------------- final: LN(last token) @ fc_w + fc_b ------------------------- */
__global__ void final_kernel(const float* __restrict__ h, const float* __restrict__ gn,
                             const float* __restrict__ bn, const float* __restrict__ fw,
                             const float* __restrict__ fb, float* __restrict__ out) {
    __shared__ float sbuf[32];
    __shared__ float row[DMODEL];
    int b = blockIdx.x, t = threadIdx.x;
    const float* hr = h + (size_t)(b*LL + (LL-1))*DMODEL;
    float v0 = hr[t], v1 = hr[t + 256];
    float mean = block_reduce_sum(v0 + v1, sbuf) * (1.f/DMODEL);
    float d0 = v0 - mean, d1 = v1 - mean;
    float var = block_reduce_sum(d0*d0 + d1*d1, sbuf) * (1.f/DMODEL);
    float inv = rsqrtf(var + LEPS);
    row[t]       = d0*inv*gn[t]     + bn[t];
    row[t + 256] = d1*inv*gn[t+256] + bn[t+256];
    __syncthreads();
    for (int p = t; p < NPRED; p += 256) {
        float s = fb[p];
        for (int d = 0; d < DMODEL; d++) s += row[d]*fw[(size_t)d*NPRED + p];
        out[(size_t)b*NPRED + p] = s;
    }
}

/* ------------------------- launch ------------------------- */
extern "C" void kernel_launch(void* const* d_in, const int* in_sizes, int n_in,
                              void* d_out, int out_size) {
    const float* x     = (const float*)d_in[0];
    const float* emb_w = (const float*)d_in[1];
    const float* emb_b = (const float*)d_in[2];
    const float* pe    = (const float*)d_in[3];
    const float* Wq    = (const float*)d_in[4];
    const float* bq    = (const float*)d_in[5];
    const float* Wk    = (const float*)d_in[6];
    const float* bk    = (const float*)d_in[7];
    const float* Wv    = (const float*)d_in[8];
    const float* bv    = (const float*)d_in[9];
    const float* Wo    = (const float*)d_in[10];
    const float* bo    = (const float*)d_in[11];
    const float* W1    = (const float*)d_in[12];
    const float* b1    = (const float*)d_in[13];
    const float* W2    = (const float*)d_in[14];
    const float* b2    = (const float*)d_in[15];
    const float* g1    = (const float*)d_in[16];
    const float* be1   = (const float*)d_in[17];
    const float* g2    = (const float*)d_in[18];
    const float* be2   = (const float*)d_in[19];
    const float* lm_qw = (const float*)d_in[20];
    const float* lm_qb = (const float*)d_in[21];
    const float* lm_kw = (const float*)d_in[22];
    const float* lm_kb = (const float*)d_in[23];
    const float* gn    = (const float*)d_in[24];
    const float* bn    = (const float*)d_in[25];
    const float* fc_w  = (const float*)d_in[26];
    const float* fc_b  = (const float*)d_in[27];
    float* out = (float*)d_out;

    float *h, *hr, *q, *k, *v, *ctx, *y, *qp, *kp, *ffn;
    float *wqr, *wkr, *wvr, *wor, *w1r, *w2r;
    cudaGetSymbolAddress((void**)&h,   g_h);
    cudaGetSymbolAddress((void**)&hr,  g_hr);
    cudaGetSymbolAddress((void**)&q,   g_q);
    cudaGetSymbolAddress((void**)&k,   g_k);
    cudaGetSymbolAddress((void**)&v,   g_v);
    cudaGetSymbolAddress((void**)&ctx, g_ctx);
    cudaGetSymbolAddress((void**)&y,   g_y);
    cudaGetSymbolAddress((void**)&qp,  g_qp);
    cudaGetSymbolAddress((void**)&kp,  g_kp);
    cudaGetSymbolAddress((void**)&ffn, g_ffn);
    cudaGetSymbolAddress((void**)&wqr, g_wqr);
    cudaGetSymbolAddress((void**)&wkr, g_wkr);
    cudaGetSymbolAddress((void**)&wvr, g_wvr);
    cudaGetSymbolAddress((void**)&wor, g_wor);
    cudaGetSymbolAddress((void**)&w1r, g_w1r);
    cudaGetSymbolAddress((void**)&w2r, g_w2r);

    cudaFuncSetAttribute(flash_kernel,
                         cudaFuncAttributeMaxDynamicSharedMemorySize, FLASH_SMEM_BYTES);

    /* round weights once per launch */
    int n4_sq = NLAYERS*DMODEL*DMODEL/4;   /* 262144 */
    int n4_ff = NLAYERS*DMODEL*DFF/4;      /* 1048576 */
    round_kernel<<<592, 256>>>((const float4*)Wq, (float4*)wqr, n4_sq);
    round_kernel<<<592, 256>>>((const float4*)Wk, (float4*)wkr, n4_sq);
    round_kernel<<<592, 256>>>((const float4*)Wv, (float4*)wvr, n4_sq);
    round_kernel<<<592, 256>>>((const float4*)Wo, (float4*)wor, n4_sq);
    round_kernel<<<592, 256>>>((const float4*)W1, (float4*)w1r, n4_ff);
    round_kernel<<<592, 256>>>((const float4*)W2, (float4*)w2r, n4_ff);

    embed_kernel<<<ROWS, 256>>>(x, emb_w, emb_b, pe, h, hr);

    dim3 g512(DMODEL/128, (ROWS + 127)/128);
    dim3 gff (DFF/128,    (ROWS + 127)/128);
    dim3 gfl (8, BB*HH);
    dim3 glm (ROWS, 2);

    for (int i = 0; i < NLAYERS; i++) {
        const float* Wq_i = wqr + (size_t)i*DMODEL*DMODEL;
        const float* Wk_i = wkr + (size_t)i*DMODEL*DMODEL;
        const float* Wv_i = wvr + (size_t)i*DMODEL*DMODEL;
        const float* Wo_i = wor + (size_t)i*DMODEL*DMODEL;
        const float* bq_i = bq + (size_t)i*DMODEL;
        const float* bk_i = bk + (size_t)i*DMODEL;
        const float* bv_i = bv + (size_t)i*DMODEL;
        const float* bo_i = bo + (size_t)i*DMODEL;
        const float* W1_i = w1r + (size_t)i*DMODEL*DFF;
        const float* b1_i = b1 + (size_t)i*DFF;
        const float* W2_i = w2r + (size_t)i*DFF*DMODEL;
        const float* b2_i = b2 + (size_t)i*DMODEL;
        const float* g1_i = g1 + (size_t)i*DMODEL;
        const float* be1_i= be1+ (size_t)i*DMODEL;
        const float* g2_i = g2 + (size_t)i*DMODEL;
        const float* be2_i= be2+ (size_t)i*DMODEL;

        gemm_tf32<0,0><<<g512, 256>>>(hr, Wq_i, bq_i, q, ROWS, DMODEL, DMODEL);
        gemm_tf32<0,0><<<g512, 256>>>(hr, Wk_i, bk_i, k, ROWS, DMODEL, DMODEL);
        gemm_tf32<0,0><<<g512, 256>>>(hr, Wv_i, bv_i, v, ROWS, DMODEL, DMODEL);

        lmproj_kernel<<<glm, 128>>>(q, k, lm_qw, lm_qb, lm_kw, lm_kb, qp, kp);

        flash_kernel<<<gfl, 256, FLASH_SMEM_BYTES>>>(q, k, v, qp, kp, ctx);

        gemm_tf32<0,0><<<g512, 256>>>(ctx, Wo_i, bo_i, q, ROWS, DMODEL, DMODEL);
        ln_residual_kernel<<<ROWS, 256>>>(h, hr, q, g1_i, be1_i);

        gemm_tf32<1,1><<<gff, 256>>>(hr, W1_i, b1_i, ffn, ROWS, DFF, DMODEL);
        gemm_tf32<0,0><<<g512, 256>>>(ffn, W2_i, b2_i, y, ROWS, DMODEL, DFF);
        double_ln_kernel<<<ROWS, 256>>>(h, hr, y, g2_i, be2_i);
    }

    final_kernel<<<BB, 256>>>(h, gn, bn, fc_w, fc_b, out);
    (void)in_sizes; (void)n_in; (void)out_size;
}